// round 1
// baseline (speedup 1.0000x reference)
#include <cuda_runtime.h>

// ---------------- problem constants ----------------
#define BB   8
#define TT   2048
#define CC   1024
#define EE   8
#define HH   4096
#define CAP  320                 // int(T/E * 1.25)
#define NTOK (BB * TT)           // 16384 tokens
#define NASN (NTOK * 2)          // 32768 assignments (top-2)
#define ROWSE (BB * CAP)         // 2560 rows per expert

// ---------------- scratch (static device globals; no runtime alloc) ----------------
static __device__ float g_h1[(size_t)NTOK * HH];          // 268 MB
static __device__ float g_h2[(size_t)NTOK * HH];          // 268 MB
static __device__ float g_xe[(size_t)EE * ROWSE * CC];    //  84 MB
static __device__ float g_he[(size_t)EE * ROWSE * HH];    // 336 MB
static __device__ float g_ye[(size_t)EE * ROWSE * CC];    //  84 MB
static __device__ int   g_expert[NASN];
static __device__ float g_gate[NASN];
static __device__ int   g_pos[NASN];                      // slot within (b,e); -1 = dropped

// ---------------- SGEMM: C = act(A @ B + bias), row-major, fp32 ----------------
// BM=BN=128, BK=8, 256 threads, 8x8 per-thread microtile, register-staged
// double buffering of global loads. M % 128 == 0, N % 128 == 0, K % 8 == 0.
template <bool RELU>
__global__ __launch_bounds__(256)
void sgemm_bias(const float* __restrict__ Ag, const float* __restrict__ Bg,
                const float* __restrict__ biasg, float* __restrict__ Cg,
                int M, int N, int K,
                long long sA, long long sB, long long sBias, long long sC)
{
    const int tid = threadIdx.x;
    const float* A    = Ag + blockIdx.z * sA + (size_t)blockIdx.y * 128 * K;
    const float* Bp   = Bg + blockIdx.z * sB + blockIdx.x * 128;
    const float* bias = biasg + blockIdx.z * sBias + blockIdx.x * 128;
    float*       Cp   = Cg + blockIdx.z * sC + (size_t)blockIdx.y * 128 * N + blockIdx.x * 128;

    __shared__ float As[8][128];   // transposed A tile: As[k][m]
    __shared__ float Bs[8][128];   // Bs[k][n]

    const int arow = tid >> 1;            // 0..127
    const int acol = (tid & 1) << 2;      // 0 or 4
    const int brow = tid >> 5;            // 0..7
    const int bcol = (tid & 31) << 2;     // 0..124
    const int tx   = (tid & 15) << 3;     // col base of microtile
    const int ty   = (tid >> 4) << 3;     // row base of microtile

    const float* Aptr = A  + (size_t)arow * K + acol;
    const float* Bptr = Bp + (size_t)brow * N + bcol;

    float acc[8][8];
#pragma unroll
    for (int i = 0; i < 8; ++i)
#pragma unroll
        for (int j = 0; j < 8; ++j) acc[i][j] = 0.f;

    // prologue: tile 0
    float4 a = *(const float4*)Aptr;
    float4 b = *(const float4*)Bptr;
    As[acol + 0][arow] = a.x; As[acol + 1][arow] = a.y;
    As[acol + 2][arow] = a.z; As[acol + 3][arow] = a.w;
    *(float4*)&Bs[brow][bcol] = b;
    __syncthreads();

    const int ktiles = K >> 3;
    for (int t = 1; t < ktiles; ++t) {
        a = *(const float4*)(Aptr + (t << 3));
        b = *(const float4*)(Bptr + (size_t)(t << 3) * N);
#pragma unroll
        for (int kk = 0; kk < 8; ++kk) {
            float4 a0 = *(const float4*)&As[kk][ty];
            float4 a1 = *(const float4*)&As[kk][ty + 4];
            float4 b0 = *(const float4*)&Bs[kk][tx];
            float4 b1 = *(const float4*)&Bs[kk][tx + 4];
            float am[8] = {a0.x, a0.y, a0.z, a0.w, a1.x, a1.y, a1.z, a1.w};
            float bm[8] = {b0.x, b0.y, b0.z, b0.w, b1.x, b1.y, b1.z, b1.w};
#pragma unroll
            for (int i = 0; i < 8; ++i)
#pragma unroll
                for (int j = 0; j < 8; ++j)
                    acc[i][j] += am[i] * bm[j];
        }
        __syncthreads();
        As[acol + 0][arow] = a.x; As[acol + 1][arow] = a.y;
        As[acol + 2][arow] = a.z; As[acol + 3][arow] = a.w;
        *(float4*)&Bs[brow][bcol] = b;
        __syncthreads();
    }
    // last tile
#pragma unroll
    for (int kk = 0; kk < 8; ++kk) {
        float4 a0 = *(const float4*)&As[kk][ty];
        float4 a1 = *(const float4*)&As[kk][ty + 4];
        float4 b0 = *(const float4*)&Bs[kk][tx];
        float4 b1 = *(const float4*)&Bs[kk][tx + 4];
        float am[8] = {a0.x, a0.y, a0.z, a0.w, a1.x, a1.y, a1.z, a1.w};
        float bm[8] = {b0.x, b0.y, b0.z, b0.w, b1.x, b1.y, b1.z, b1.w};
#pragma unroll
        for (int i = 0; i < 8; ++i)
#pragma unroll
            for (int j = 0; j < 8; ++j)
                acc[i][j] += am[i] * bm[j];
    }

    float4 bi0 = *(const float4*)&bias[tx];
    float4 bi1 = *(const float4*)&bias[tx + 4];
    float bv[8] = {bi0.x, bi0.y, bi0.z, bi0.w, bi1.x, bi1.y, bi1.z, bi1.w};
#pragma unroll
    for (int i = 0; i < 8; ++i) {
        float o[8];
#pragma unroll
        for (int j = 0; j < 8; ++j) {
            o[j] = acc[i][j] + bv[j];
            if (RELU) o[j] = fmaxf(o[j], 0.f);
        }
        float* crow = Cp + (size_t)(ty + i) * N + tx;
        *(float4*)crow       = make_float4(o[0], o[1], o[2], o[3]);
        *(float4*)(crow + 4) = make_float4(o[4], o[5], o[6], o[7]);
    }
}

// ---------------- router final layer: logits -> softmax -> top2 ----------------
// one warp per token; lane i accumulates 8 partial logits (rW3 row i is 8 contiguous floats)
__global__ void router_topk(const float* __restrict__ h2,
                            const float* __restrict__ rW3,
                            const float* __restrict__ rb3)
{
    const int warp = (blockIdx.x * blockDim.x + threadIdx.x) >> 5;
    const int lane = threadIdx.x & 31;
    if (warp >= NTOK) return;

    const float* hrow = h2 + (size_t)warp * HH;
    float acc[8] = {0.f, 0.f, 0.f, 0.f, 0.f, 0.f, 0.f, 0.f};
    for (int i = lane; i < HH; i += 32) {
        const float hv = hrow[i];
        const float4 w0 = *(const float4*)(rW3 + (size_t)i * 8);
        const float4 w1 = *(const float4*)(rW3 + (size_t)i * 8 + 4);
        acc[0] += hv * w0.x; acc[1] += hv * w0.y; acc[2] += hv * w0.z; acc[3] += hv * w0.w;
        acc[4] += hv * w1.x; acc[5] += hv * w1.y; acc[6] += hv * w1.z; acc[7] += hv * w1.w;
    }
#pragma unroll
    for (int e = 0; e < 8; ++e)
#pragma unroll
        for (int off = 16; off > 0; off >>= 1)
            acc[e] += __shfl_xor_sync(0xffffffffu, acc[e], off);

    if (lane == 0) {
        float lg[8];
        float mx = -1e30f;
#pragma unroll
        for (int e = 0; e < 8; ++e) { lg[e] = acc[e] + rb3[e]; mx = fmaxf(mx, lg[e]); }
        float sm[8], sum = 0.f;
#pragma unroll
        for (int e = 0; e < 8; ++e) { sm[e] = __expf(lg[e] - mx); sum += sm[e]; }
        const float inv = 1.f / sum;
#pragma unroll
        for (int e = 0; e < 8; ++e) sm[e] *= inv;

        // stable top-2 (ties -> lower index), matching lax.top_k
        int e1 = 0; float v1 = sm[0];
#pragma unroll
        for (int e = 1; e < 8; ++e) if (sm[e] > v1) { v1 = sm[e]; e1 = e; }
        int e2 = -1; float v2 = -1e30f;
#pragma unroll
        for (int e = 0; e < 8; ++e) {
            if (e == e1) continue;
            if (sm[e] > v2) { v2 = sm[e]; e2 = e; }
        }
        const int j = warp * 2;
        g_expert[j] = e1; g_gate[j] = v1;
        g_expert[j + 1] = e2; g_gate[j + 1] = v2;
    }
}

// ---------------- per-(b,e) capacity scan in (t, slot) order ----------------
__global__ void scan_capacity()
{
    const int b = blockIdx.x;
    const int e = threadIdx.x;
    if (e >= EE) return;
    const int base = b * (TT * 2);
    int cnt = 0;
    for (int i = 0; i < TT * 2; ++i) {
        if (g_expert[base + i] == e) {
            g_pos[base + i] = (cnt < CAP) ? cnt : -1;
            ++cnt;
        }
    }
}

// ---------------- gather kept tokens into per-expert rows ----------------
__global__ void scatter_x(const float* __restrict__ x)
{
    const int j = blockIdx.x;           // assignment id: (b*T + t)*2 + slot
    const int pos = g_pos[j];
    if (pos < 0) return;
    const int e = g_expert[j];
    const int b = j / (TT * 2);
    const int t = (j % (TT * 2)) >> 1;
    const float4* src = (const float4*)(x + (size_t)(b * TT + t) * CC);
    float4* dst = (float4*)(g_xe + ((size_t)e * ROWSE + b * CAP + pos) * CC);
    for (int c = threadIdx.x; c < CC / 4; c += blockDim.x) dst[c] = src[c];
}

// ---------------- combine: out = sum_slots gate * y ----------------
__global__ void combine(float* __restrict__ out)
{
    const int tok = blockIdx.x;
    const int b = tok / TT;
    const int j = tok * 2;
    const int e0 = g_expert[j],     p0 = g_pos[j];     const float w0 = g_gate[j];
    const int e1 = g_expert[j + 1], p1 = g_pos[j + 1]; const float w1 = g_gate[j + 1];
    const float4* y0 = (p0 >= 0) ? (const float4*)(g_ye + ((size_t)e0 * ROWSE + b * CAP + p0) * CC) : nullptr;
    const float4* y1 = (p1 >= 0) ? (const float4*)(g_ye + ((size_t)e1 * ROWSE + b * CAP + p1) * CC) : nullptr;
    float4* o = (float4*)(out + (size_t)tok * CC);
    for (int c = threadIdx.x; c < CC / 4; c += blockDim.x) {
        float4 acc = make_float4(0.f, 0.f, 0.f, 0.f);
        if (y0) { float4 v = y0[c]; acc.x += w0 * v.x; acc.y += w0 * v.y; acc.z += w0 * v.z; acc.w += w0 * v.w; }
        if (y1) { float4 v = y1[c]; acc.x += w1 * v.x; acc.y += w1 * v.y; acc.z += w1 * v.z; acc.w += w1 * v.w; }
        o[c] = acc;
    }
}

// ---------------- launch ----------------
extern "C" void kernel_launch(void* const* d_in, const int* in_sizes, int n_in,
                              void* d_out, int out_size)
{
    const float* x   = (const float*)d_in[0];
    const float* rW1 = (const float*)d_in[1];
    const float* rb1 = (const float*)d_in[2];
    const float* rW2 = (const float*)d_in[3];
    const float* rb2 = (const float*)d_in[4];
    const float* rW3 = (const float*)d_in[5];
    const float* rb3 = (const float*)d_in[6];
    const float* eW1 = (const float*)d_in[7];
    const float* eb1 = (const float*)d_in[8];
    const float* eW2 = (const float*)d_in[9];
    const float* eb2 = (const float*)d_in[10];
    float* out = (float*)d_out;

    float* h1; cudaGetSymbolAddress((void**)&h1, g_h1);
    float* h2; cudaGetSymbolAddress((void**)&h2, g_h2);
    float* xe; cudaGetSymbolAddress((void**)&xe, g_xe);
    float* he; cudaGetSymbolAddress((void**)&he, g_he);
    float* ye; cudaGetSymbolAddress((void**)&ye, g_ye);

    // router layer 1: h1 = relu(x @ rW1 + rb1)   [16384,1024]x[1024,4096]
    sgemm_bias<true><<<dim3(HH / 128, NTOK / 128, 1), 256>>>(
        x, rW1, rb1, h1, NTOK, HH, CC, 0, 0, 0, 0);
    // router layer 2: h2 = relu(h1 @ rW2 + rb2)  [16384,4096]x[4096,4096]
    sgemm_bias<true><<<dim3(HH / 128, NTOK / 128, 1), 256>>>(
        h1, rW2, rb2, h2, NTOK, HH, HH, 0, 0, 0, 0);
    // logits + softmax + top2
    router_topk<<<(NTOK * 32) / 256, 256>>>(h2, rW3, rb3);
    // capacity positions in reference order
    scan_capacity<<<BB, 32>>>();
    // dispatch kept tokens
    scatter_x<<<NASN, 256>>>(x);
    // expert layer 1: he = relu(xe @ eW1[e] + eb1[e])   [2560,1024]x[1024,4096] per expert
    sgemm_bias<true><<<dim3(HH / 128, ROWSE / 128, EE), 256>>>(
        xe, eW1, eb1, he, ROWSE, HH, CC,
        (long long)ROWSE * CC, (long long)CC * HH, HH, (long long)ROWSE * HH);
    // expert layer 2: ye = he @ eW2[e] + eb2[e]         [2560,4096]x[4096,1024] per expert
    sgemm_bias<false><<<dim3(CC / 128, ROWSE / 128, EE), 256>>>(
        he, eW2, eb2, ye, ROWSE, CC, HH,
        (long long)ROWSE * HH, (long long)HH * CC, CC, (long long)ROWSE * CC);
    // combine
    combine<<<NTOK, 256>>>(out);
}

// round 3
// speedup vs baseline: 1.3904x; 1.3904x over previous
#include <cuda_runtime.h>
#include <cstdint>

// ---------------- problem constants ----------------
#define BB   8
#define TT   2048
#define CC   1024
#define EE   8
#define HH   4096
#define CAP  320
#define NTOK (BB * TT)
#define NASN (NTOK * 2)
#define ROWSE (BB * CAP)          // 2560

// ---------------- scratch ----------------
static __device__ float g_h1[(size_t)NTOK * HH];
static __device__ float g_h2[(size_t)NTOK * HH];
static __device__ float g_xe[(size_t)EE * ROWSE * CC];
static __device__ float g_he[(size_t)EE * ROWSE * HH];
static __device__ float g_ye[(size_t)EE * ROWSE * CC];
static __device__ float g_rW1t[(size_t)HH * CC];
static __device__ float g_rW2t[(size_t)HH * HH];
static __device__ float g_eW1t[(size_t)EE * HH * CC];
static __device__ float g_eW2t[(size_t)EE * CC * HH];
static __device__ int   g_expert[NASN];
static __device__ float g_gate[NASN];
static __device__ int   g_pos[NASN];

// ---------------- helpers ----------------
__device__ __forceinline__ float tf32_rna(float x) {
    uint32_t u;
    asm("cvt.rna.tf32.f32 %0, %1;" : "=r"(u) : "f"(x));
    return __uint_as_float(u);
}
__device__ __forceinline__ void split4(float4 v, float4& h, float4& l) {
    h.x = tf32_rna(v.x); l.x = tf32_rna(v.x - h.x);
    h.y = tf32_rna(v.y); l.y = tf32_rna(v.y - h.y);
    h.z = tf32_rna(v.z); l.z = tf32_rna(v.z - h.z);
    h.w = tf32_rna(v.w); l.w = tf32_rna(v.w - h.w);
}
__device__ __forceinline__ void mma_tf32(float* c, const uint32_t* a, uint32_t b0, uint32_t b1) {
    asm("mma.sync.aligned.m16n8k8.row.col.f32.tf32.tf32.f32 "
        "{%0,%1,%2,%3}, {%4,%5,%6,%7}, {%8,%9}, {%0,%1,%2,%3};"
        : "+f"(c[0]), "+f"(c[1]), "+f"(c[2]), "+f"(c[3])
        : "r"(a[0]), "r"(a[1]), "r"(a[2]), "r"(a[3]), "r"(b0), "r"(b1));
}

// smem tile: [128 rows][20 floats] (pad 16->20 for conflict-free fragment lds)
#define PAD 20
#define TILE_F (128 * PAD)                 // floats per (hi or lo) copy
#define STAGE_F (4 * TILE_F)               // Ahi, Alo, Bhi, Blo
#define SMEM_FLOATS (2 * STAGE_F)          // double buffered
// offsets within a stage
#define OFF_AHI 0
#define OFF_ALO TILE_F
#define OFF_BHI (2 * TILE_F)
#define OFF_BLO (3 * TILE_F)

// ---------------- 3xTF32 mma.sync GEMM: C = act(A @ Bt^T + bias) ----------------
// A [M,K] row-major, Bt [N,K] row-major, C [M,N]. M%128==0, N%128==0, K%16==0.
template <bool RELU>
__global__ __launch_bounds__(256, 2)
void mma_gemm(const float* __restrict__ Ag, const float* __restrict__ Btg,
              const float* __restrict__ biasg, float* __restrict__ Cg,
              int N, int K,
              long long sA, long long sB, long long sBias, long long sC)
{
    extern __shared__ float smem[];
    const int tid  = threadIdx.x;
    const int wid  = tid >> 5;
    const int lane = tid & 31;
    const int g    = lane >> 2;     // group id 0..7
    const int q    = lane & 3;      // thread-in-group 0..3

    const float* A    = Ag    + blockIdx.z * sA + (size_t)blockIdx.y * 128 * K;
    const float* Bt   = Btg   + blockIdx.z * sB + (size_t)blockIdx.x * 128 * K;
    const float* bias = biasg + blockIdx.z * sBias + blockIdx.x * 128;
    float*       C    = Cg    + blockIdx.z * sC + (size_t)blockIdx.y * 128 * N + blockIdx.x * 128;

    // warp tile: wm in {0,32,64,96}, wn in {0,64}
    const int wm = (wid & 3) * 32;
    const int wn = (wid >> 2) * 64;

    // ldg mapping: row = tid>>1 (0..127), kb = (tid&1)*8
    const int row = tid >> 1;
    const int kb  = (tid & 1) << 3;
    const float* Ap = A  + (size_t)row * K + kb;
    const float* Bp = Bt + (size_t)row * K + kb;
    const int stsOff = row * PAD + kb;      // float index within tile copy

    float acc[2][8][4];
#pragma unroll
    for (int mt = 0; mt < 2; ++mt)
#pragma unroll
        for (int nt = 0; nt < 8; ++nt)
#pragma unroll
            for (int i = 0; i < 4; ++i) acc[mt][nt][i] = 0.f;

    const int T = K >> 4;

    // prologue: load + split + sts chunk 0 into stage 0
    float4 ra0 = ((const float4*)Ap)[0], ra1 = ((const float4*)Ap)[1];
    float4 rb0 = ((const float4*)Bp)[0], rb1 = ((const float4*)Bp)[1];
    {
        float4 h, l;
        split4(ra0, h, l);
        *(float4*)(smem + OFF_AHI + stsOff) = h; *(float4*)(smem + OFF_ALO + stsOff) = l;
        split4(ra1, h, l);
        *(float4*)(smem + OFF_AHI + stsOff + 4) = h; *(float4*)(smem + OFF_ALO + stsOff + 4) = l;
        split4(rb0, h, l);
        *(float4*)(smem + OFF_BHI + stsOff) = h; *(float4*)(smem + OFF_BLO + stsOff) = l;
        split4(rb1, h, l);
        *(float4*)(smem + OFF_BHI + stsOff + 4) = h; *(float4*)(smem + OFF_BLO + stsOff + 4) = l;
    }
    __syncthreads();

    for (int t = 0; t < T; ++t) {
        const bool more = (t + 1 < T);
        if (more) {
            const float* Apt = Ap + ((t + 1) << 4);
            const float* Bpt = Bp + ((t + 1) << 4);
            ra0 = ((const float4*)Apt)[0]; ra1 = ((const float4*)Apt)[1];
            rb0 = ((const float4*)Bpt)[0]; rb1 = ((const float4*)Bpt)[1];
        }

        const float* st = smem + (t & 1) * STAGE_F;
        const uint32_t* sAhi = (const uint32_t*)(st + OFF_AHI);
        const uint32_t* sAlo = (const uint32_t*)(st + OFF_ALO);
        const uint32_t* sBhi = (const uint32_t*)(st + OFF_BHI);
        const uint32_t* sBlo = (const uint32_t*)(st + OFF_BLO);

#pragma unroll
        for (int ks = 0; ks < 2; ++ks) {
            const int k0 = ks << 3;
            uint32_t ah[2][4], al[2][4];
#pragma unroll
            for (int mt = 0; mt < 2; ++mt) {
                const int r = wm + 16 * mt + g;
                const int i0 = r * PAD + k0 + q;
                ah[mt][0] = sAhi[i0];
                ah[mt][1] = sAhi[i0 + 8 * PAD];
                ah[mt][2] = sAhi[i0 + 4];
                ah[mt][3] = sAhi[i0 + 8 * PAD + 4];
                al[mt][0] = sAlo[i0];
                al[mt][1] = sAlo[i0 + 8 * PAD];
                al[mt][2] = sAlo[i0 + 4];
                al[mt][3] = sAlo[i0 + 8 * PAD + 4];
            }
#pragma unroll
            for (int nt = 0; nt < 8; ++nt) {
                const int n = wn + 8 * nt + g;
                const int j0 = n * PAD + k0 + q;
                const uint32_t bh0 = sBhi[j0], bh1 = sBhi[j0 + 4];
                const uint32_t bl0 = sBlo[j0], bl1 = sBlo[j0 + 4];
#pragma unroll
                for (int mt = 0; mt < 2; ++mt) {
                    mma_tf32(acc[mt][nt], ah[mt], bh0, bh1);
                    mma_tf32(acc[mt][nt], ah[mt], bl0, bl1);
                    mma_tf32(acc[mt][nt], al[mt], bh0, bh1);
                }
            }
        }

        if (more) {
            float* dst = smem + ((t + 1) & 1) * STAGE_F;
            float4 h, l;
            split4(ra0, h, l);
            *(float4*)(dst + OFF_AHI + stsOff) = h; *(float4*)(dst + OFF_ALO + stsOff) = l;
            split4(ra1, h, l);
            *(float4*)(dst + OFF_AHI + stsOff + 4) = h; *(float4*)(dst + OFF_ALO + stsOff + 4) = l;
            split4(rb0, h, l);
            *(float4*)(dst + OFF_BHI + stsOff) = h; *(float4*)(dst + OFF_BLO + stsOff) = l;
            split4(rb1, h, l);
            *(float4*)(dst + OFF_BHI + stsOff + 4) = h; *(float4*)(dst + OFF_BLO + stsOff + 4) = l;
        }
        __syncthreads();
    }

    // epilogue: c0/c1 at (row, 2q), (row, 2q+1); c2/c3 at row+8
#pragma unroll
    for (int nt = 0; nt < 8; ++nt) {
        const int c = wn + 8 * nt + 2 * q;
        const float b0 = bias[c], b1 = bias[c + 1];
#pragma unroll
        for (int mt = 0; mt < 2; ++mt) {
            const int r = wm + 16 * mt + g;
            float2 v0, v1;
            v0.x = acc[mt][nt][0] + b0; v0.y = acc[mt][nt][1] + b1;
            v1.x = acc[mt][nt][2] + b0; v1.y = acc[mt][nt][3] + b1;
            if (RELU) {
                v0.x = fmaxf(v0.x, 0.f); v0.y = fmaxf(v0.y, 0.f);
                v1.x = fmaxf(v1.x, 0.f); v1.y = fmaxf(v1.y, 0.f);
            }
            *(float2*)(C + (size_t)r * N + c)       = v0;
            *(float2*)(C + (size_t)(r + 8) * N + c) = v1;
        }
    }
}

// ---------------- weight transpose: W [K,N] -> Wt [N,K] ----------------
__global__ void transpose_w(const float* __restrict__ W, float* __restrict__ Wt,
                            int K, int N, long long sIn, long long sOut)
{
    __shared__ float s[32][33];
    const float* Wz = W + blockIdx.z * sIn;
    float* Wtz = Wt + blockIdx.z * sOut;
    const int nb = blockIdx.x * 32, kbv = blockIdx.y * 32;
    const int tx = threadIdx.x, ty = threadIdx.y;
#pragma unroll
    for (int j = 0; j < 32; j += 8) s[ty + j][tx] = Wz[(size_t)(kbv + ty + j) * N + nb + tx];
    __syncthreads();
#pragma unroll
    for (int j = 0; j < 32; j += 8) Wtz[(size_t)(nb + ty + j) * K + kbv + tx] = s[tx][ty + j];
}

// ---------------- router final layer: logits -> softmax -> top2 ----------------
__global__ void router_topk(const float* __restrict__ h2,
                            const float* __restrict__ rW3,
                            const float* __restrict__ rb3)
{
    const int warp = (blockIdx.x * blockDim.x + threadIdx.x) >> 5;
    const int lane = threadIdx.x & 31;
    if (warp >= NTOK) return;
    const float* hrow = h2 + (size_t)warp * HH;
    float acc[8] = {0.f, 0.f, 0.f, 0.f, 0.f, 0.f, 0.f, 0.f};
    for (int i = lane; i < HH; i += 32) {
        const float hv = hrow[i];
        const float4 w0 = *(const float4*)(rW3 + (size_t)i * 8);
        const float4 w1 = *(const float4*)(rW3 + (size_t)i * 8 + 4);
        acc[0] += hv * w0.x; acc[1] += hv * w0.y; acc[2] += hv * w0.z; acc[3] += hv * w0.w;
        acc[4] += hv * w1.x; acc[5] += hv * w1.y; acc[6] += hv * w1.z; acc[7] += hv * w1.w;
    }
#pragma unroll
    for (int e = 0; e < 8; ++e)
#pragma unroll
        for (int off = 16; off > 0; off >>= 1)
            acc[e] += __shfl_xor_sync(0xffffffffu, acc[e], off);
    if (lane == 0) {
        float lg[8], mx = -1e30f;
#pragma unroll
        for (int e = 0; e < 8; ++e) { lg[e] = acc[e] + rb3[e]; mx = fmaxf(mx, lg[e]); }
        float sm[8], sum = 0.f;
#pragma unroll
        for (int e = 0; e < 8; ++e) { sm[e] = __expf(lg[e] - mx); sum += sm[e]; }
        const float inv = 1.f / sum;
#pragma unroll
        for (int e = 0; e < 8; ++e) sm[e] *= inv;
        int e1 = 0; float v1 = sm[0];
#pragma unroll
        for (int e = 1; e < 8; ++e) if (sm[e] > v1) { v1 = sm[e]; e1 = e; }
        int e2 = -1; float v2 = -1e30f;
#pragma unroll
        for (int e = 0; e < 8; ++e) {
            if (e == e1) continue;
            if (sm[e] > v2) { v2 = sm[e]; e2 = e; }
        }
        const int j = warp * 2;
        g_expert[j] = e1;     g_gate[j] = v1;
        g_expert[j + 1] = e2; g_gate[j + 1] = v2;
    }
}

// ---------------- per-(b,e) capacity scan (smem-staged) ----------------
__global__ void scan_capacity()
{
    __shared__ int se[TT * 2];
    const int b = blockIdx.x;
    const int base = b * (TT * 2);
    for (int i = threadIdx.x; i < TT * 2; i += blockDim.x) se[i] = g_expert[base + i];
    __syncthreads();
    const int e = threadIdx.x;
    if (e < EE) {
        int cnt = 0;
        for (int i = 0; i < TT * 2; ++i)
            if (se[i] == e) { g_pos[base + i] = (cnt < CAP) ? cnt : -1; ++cnt; }
    }
}

// ---------------- gather kept tokens ----------------
__global__ void scatter_x(const float* __restrict__ x)
{
    const int j = blockIdx.x;
    const int pos = g_pos[j];
    if (pos < 0) return;
    const int e = g_expert[j];
    const int b = j / (TT * 2);
    const int t = (j % (TT * 2)) >> 1;
    const float4* src = (const float4*)(x + (size_t)(b * TT + t) * CC);
    float4* dst = (float4*)(g_xe + ((size_t)e * ROWSE + b * CAP + pos) * CC);
    for (int c = threadIdx.x; c < CC / 4; c += blockDim.x) dst[c] = src[c];
}

// ---------------- combine ----------------
__global__ void combine(float* __restrict__ out)
{
    const int tok = blockIdx.x;
    const int b = tok / TT;
    const int j = tok * 2;
    const int e0 = g_expert[j],     p0 = g_pos[j];     const float w0 = g_gate[j];
    const int e1 = g_expert[j + 1], p1 = g_pos[j + 1]; const float w1 = g_gate[j + 1];
    const float4* y0 = (p0 >= 0) ? (const float4*)(g_ye + ((size_t)e0 * ROWSE + b * CAP + p0) * CC) : nullptr;
    const float4* y1 = (p1 >= 0) ? (const float4*)(g_ye + ((size_t)e1 * ROWSE + b * CAP + p1) * CC) : nullptr;
    float4* o = (float4*)(out + (size_t)tok * CC);
    for (int c = threadIdx.x; c < CC / 4; c += blockDim.x) {
        float4 acc = make_float4(0.f, 0.f, 0.f, 0.f);
        if (y0) { float4 v = y0[c]; acc.x += w0 * v.x; acc.y += w0 * v.y; acc.z += w0 * v.z; acc.w += w0 * v.w; }
        if (y1) { float4 v = y1[c]; acc.x += w1 * v.x; acc.y += w1 * v.y; acc.z += w1 * v.z; acc.w += w1 * v.w; }
        o[c] = acc;
    }
}

// ---------------- launch ----------------
extern "C" void kernel_launch(void* const* d_in, const int* in_sizes, int n_in,
                              void* d_out, int out_size)
{
    const float* x   = (const float*)d_in[0];
    const float* rW1 = (const float*)d_in[1];
    const float* rb1 = (const float*)d_in[2];
    const float* rW2 = (const float*)d_in[3];
    const float* rb2 = (const float*)d_in[4];
    const float* rW3 = (const float*)d_in[5];
    const float* rb3 = (const float*)d_in[6];
    const float* eW1 = (const float*)d_in[7];
    const float* eb1 = (const float*)d_in[8];
    const float* eW2 = (const float*)d_in[9];
    const float* eb2 = (const float*)d_in[10];
    float* out = (float*)d_out;

    float *h1, *h2, *xe, *he, *ye, *rW1t, *rW2t, *eW1t, *eW2t;
    cudaGetSymbolAddress((void**)&h1, g_h1);
    cudaGetSymbolAddress((void**)&h2, g_h2);
    cudaGetSymbolAddress((void**)&xe, g_xe);
    cudaGetSymbolAddress((void**)&he, g_he);
    cudaGetSymbolAddress((void**)&ye, g_ye);
    cudaGetSymbolAddress((void**)&rW1t, g_rW1t);
    cudaGetSymbolAddress((void**)&rW2t, g_rW2t);
    cudaGetSymbolAddress((void**)&eW1t, g_eW1t);
    cudaGetSymbolAddress((void**)&eW2t, g_eW2t);

    const int smemBytes = SMEM_FLOATS * sizeof(float);   // 80 KB
    cudaFuncSetAttribute(mma_gemm<true>,  cudaFuncAttributeMaxDynamicSharedMemorySize, smemBytes);
    cudaFuncSetAttribute(mma_gemm<false>, cudaFuncAttributeMaxDynamicSharedMemorySize, smemBytes);

    // weight transposes: W[K,N] -> Wt[N,K]
    transpose_w<<<dim3(HH / 32, CC / 32, 1),  dim3(32, 8)>>>(rW1, rW1t, CC, HH, 0, 0);
    transpose_w<<<dim3(HH / 32, HH / 32, 1),  dim3(32, 8)>>>(rW2, rW2t, HH, HH, 0, 0);
    transpose_w<<<dim3(HH / 32, CC / 32, EE), dim3(32, 8)>>>(eW1, eW1t, CC, HH,
        (long long)CC * HH, (long long)HH * CC);
    transpose_w<<<dim3(CC / 32, HH / 32, EE), dim3(32, 8)>>>(eW2, eW2t, HH, CC,
        (long long)HH * CC, (long long)CC * HH);

    // router layer 1: h1 = relu(x @ rW1 + rb1)
    mma_gemm<true><<<dim3(HH / 128, NTOK / 128, 1), 256, smemBytes>>>(
        x, rW1t, rb1, h1, HH, CC, 0, 0, 0, 0);
    // router layer 2: h2 = relu(h1 @ rW2 + rb2)
    mma_gemm<true><<<dim3(HH / 128, NTOK / 128, 1), 256, smemBytes>>>(
        h1, rW2t, rb2, h2, HH, HH, 0, 0, 0, 0);
    // logits + softmax + top2
    router_topk<<<(NTOK * 32) / 256, 256>>>(h2, rW3, rb3);
    // capacity positions
    scan_capacity<<<BB, 256>>>();
    // dispatch
    scatter_x<<<NASN, 256>>>(x);
    // expert layer 1: he = relu(xe @ eW1[e] + eb1[e])
    mma_gemm<true><<<dim3(HH / 128, ROWSE / 128, EE), 256, smemBytes>>>(
        xe, eW1t, eb1, he, HH, CC,
        (long long)ROWSE * CC, (long long)HH * CC, HH, (long long)ROWSE * HH);
    // expert layer 2: ye = he @ eW2[e] + eb2[e]
    mma_gemm<false><<<dim3(CC / 128, ROWSE / 128, EE), 256, smemBytes>>>(
        he, eW2t, eb2, ye, CC, HH,
        (long long)ROWSE * HH, (long long)CC * HH, CC, (long long)ROWSE * CC);
    // combine
    combine<<<NTOK, 256>>>(out);
}

// round 4
// speedup vs baseline: 1.3942x; 1.0028x over previous
#include <cuda_runtime.h>
#include <cstdint>

// ---------------- problem constants ----------------
#define BB   8
#define TT   2048
#define CC   1024
#define EE   8
#define HH   4096
#define CAP  320
#define NTOK (BB * TT)
#define NASN (NTOK * 2)
#define ROWSE (BB * CAP)          // 2560

// ---------------- scratch ----------------
static __device__ float g_h1[(size_t)NTOK * HH];
static __device__ float g_h2[(size_t)NTOK * HH];
static __device__ float g_xe[(size_t)EE * ROWSE * CC];
static __device__ float g_he[(size_t)EE * ROWSE * HH];
static __device__ float g_ye[(size_t)EE * ROWSE * CC];
static __device__ float g_rW1t[(size_t)HH * CC];
static __device__ float g_rW2t[(size_t)HH * HH];
static __device__ float g_eW1t[(size_t)EE * HH * CC];
static __device__ float g_eW2t[(size_t)EE * CC * HH];
static __device__ int   g_expert[NASN];
static __device__ float g_gate[NASN];
static __device__ int   g_pos[NASN];

// ---------------- helpers ----------------
__device__ __forceinline__ float tf32_rna(float x) {
    uint32_t u;
    asm("cvt.rna.tf32.f32 %0, %1;" : "=r"(u) : "f"(x));
    return __uint_as_float(u);
}
__device__ __forceinline__ void split1(float v, uint32_t& h, uint32_t& l) {
    const float hf = tf32_rna(v);
    h = __float_as_uint(hf);
    l = __float_as_uint(tf32_rna(v - hf));
}
__device__ __forceinline__ void mma_tf32(float* c, const uint32_t* a, uint32_t b0, uint32_t b1) {
    asm("mma.sync.aligned.m16n8k8.row.col.f32.tf32.tf32.f32 "
        "{%0,%1,%2,%3}, {%4,%5,%6,%7}, {%8,%9}, {%0,%1,%2,%3};"
        : "+f"(c[0]), "+f"(c[1]), "+f"(c[2]), "+f"(c[3])
        : "r"(a[0]), "r"(a[1]), "r"(a[2]), "r"(a[3]), "r"(b0), "r"(b1));
}

// smem tile: [128 rows][20 floats] (pad 16->20 for conflict-free fragment lds)
#define PAD 20
#define TILE_F (128 * PAD)                 // floats per fp32 tile (A or B)
#define STAGE_F (2 * TILE_F)               // A, B (raw fp32, single copy)
#define SMEM_FLOATS (2 * STAGE_F)          // double buffered (40 KB)
#define OFF_A 0
#define OFF_B TILE_F

// ---------------- 3xTF32 mma.sync GEMM: C = act(A @ Bt^T + bias) ----------------
// A [M,K] row-major, Bt [N,K] row-major, C [M,N]. M%128==0, N%128==0, K%16==0.
// fp32 tiles in smem (one copy); hi/lo tf32 split done in registers.
template <bool RELU>
__global__ __launch_bounds__(256, 2)
void mma_gemm(const float* __restrict__ Ag, const float* __restrict__ Btg,
              const float* __restrict__ biasg, float* __restrict__ Cg,
              int N, int K,
              long long sA, long long sB, long long sBias, long long sC)
{
    extern __shared__ float smem[];
    const int tid  = threadIdx.x;
    const int wid  = tid >> 5;
    const int lane = tid & 31;
    const int g    = lane >> 2;     // group id 0..7
    const int q    = lane & 3;      // thread-in-group 0..3

    const float* A    = Ag    + blockIdx.z * sA + (size_t)blockIdx.y * 128 * K;
    const float* Bt   = Btg   + blockIdx.z * sB + (size_t)blockIdx.x * 128 * K;
    const float* bias = biasg + blockIdx.z * sBias + blockIdx.x * 128;
    float*       C    = Cg    + blockIdx.z * sC + (size_t)blockIdx.y * 128 * N + blockIdx.x * 128;

    // warp tile: wm in {0,32,64,96}, wn in {0,64}
    const int wm = (wid & 3) * 32;
    const int wn = (wid >> 2) * 64;

    // ldg mapping: row = tid>>1 (0..127), kb = (tid&1)*8
    const int row = tid >> 1;
    const int kb  = (tid & 1) << 3;
    const float* Ap = A  + (size_t)row * K + kb;
    const float* Bp = Bt + (size_t)row * K + kb;
    const int stsOff = row * PAD + kb;

    float acc[2][8][4];
#pragma unroll
    for (int mt = 0; mt < 2; ++mt)
#pragma unroll
        for (int nt = 0; nt < 8; ++nt)
#pragma unroll
            for (int i = 0; i < 4; ++i) acc[mt][nt][i] = 0.f;

    const int T = K >> 4;

    // prologue
    float4 ra0 = ((const float4*)Ap)[0], ra1 = ((const float4*)Ap)[1];
    float4 rb0 = ((const float4*)Bp)[0], rb1 = ((const float4*)Bp)[1];
    *(float4*)(smem + OFF_A + stsOff)     = ra0;
    *(float4*)(smem + OFF_A + stsOff + 4) = ra1;
    *(float4*)(smem + OFF_B + stsOff)     = rb0;
    *(float4*)(smem + OFF_B + stsOff + 4) = rb1;
    __syncthreads();

    for (int t = 0; t < T; ++t) {
        const bool more = (t + 1 < T);
        if (more) {
            const float* Apt = Ap + ((t + 1) << 4);
            const float* Bpt = Bp + ((t + 1) << 4);
            ra0 = ((const float4*)Apt)[0]; ra1 = ((const float4*)Apt)[1];
            rb0 = ((const float4*)Bpt)[0]; rb1 = ((const float4*)Bpt)[1];
        }

        const float* st = smem + (t & 1) * STAGE_F;
        const float* sTA = st + OFF_A;
        const float* sTB = st + OFF_B;

#pragma unroll
        for (int ks = 0; ks < 2; ++ks) {
            const int k0 = ks << 3;
            uint32_t ah[2][4], al[2][4];
#pragma unroll
            for (int mt = 0; mt < 2; ++mt) {
                const int i0 = (wm + 16 * mt + g) * PAD + k0 + q;
                split1(sTA[i0],               ah[mt][0], al[mt][0]);
                split1(sTA[i0 + 8 * PAD],     ah[mt][1], al[mt][1]);
                split1(sTA[i0 + 4],           ah[mt][2], al[mt][2]);
                split1(sTA[i0 + 8 * PAD + 4], ah[mt][3], al[mt][3]);
            }
#pragma unroll
            for (int nt = 0; nt < 8; ++nt) {
                const int j0 = (wn + 8 * nt + g) * PAD + k0 + q;
                uint32_t bh0, bl0, bh1, bl1;
                split1(sTB[j0],     bh0, bl0);
                split1(sTB[j0 + 4], bh1, bl1);
#pragma unroll
                for (int mt = 0; mt < 2; ++mt) {
                    mma_tf32(acc[mt][nt], ah[mt], bh0, bh1);
                    mma_tf32(acc[mt][nt], ah[mt], bl0, bl1);
                    mma_tf32(acc[mt][nt], al[mt], bh0, bh1);
                }
            }
        }

        if (more) {
            float* dst = smem + ((t + 1) & 1) * STAGE_F;
            *(float4*)(dst + OFF_A + stsOff)     = ra0;
            *(float4*)(dst + OFF_A + stsOff + 4) = ra1;
            *(float4*)(dst + OFF_B + stsOff)     = rb0;
            *(float4*)(dst + OFF_B + stsOff + 4) = rb1;
        }
        __syncthreads();
    }

    // epilogue: c0/c1 at (row, 2q), (row, 2q+1); c2/c3 at row+8
#pragma unroll
    for (int nt = 0; nt < 8; ++nt) {
        const int c = wn + 8 * nt + 2 * q;
        const float b0 = bias[c], b1 = bias[c + 1];
#pragma unroll
        for (int mt = 0; mt < 2; ++mt) {
            const int r = wm + 16 * mt + g;
            float2 v0, v1;
            v0.x = acc[mt][nt][0] + b0; v0.y = acc[mt][nt][1] + b1;
            v1.x = acc[mt][nt][2] + b0; v1.y = acc[mt][nt][3] + b1;
            if (RELU) {
                v0.x = fmaxf(v0.x, 0.f); v0.y = fmaxf(v0.y, 0.f);
                v1.x = fmaxf(v1.x, 0.f); v1.y = fmaxf(v1.y, 0.f);
            }
            *(float2*)(C + (size_t)r * N + c)       = v0;
            *(float2*)(C + (size_t)(r + 8) * N + c) = v1;
        }
    }
}

// ---------------- weight transpose: W [K,N] -> Wt [N,K] ----------------
__global__ void transpose_w(const float* __restrict__ W, float* __restrict__ Wt,
                            int K, int N, long long sIn, long long sOut)
{
    __shared__ float s[32][33];
    const float* Wz = W + blockIdx.z * sIn;
    float* Wtz = Wt + blockIdx.z * sOut;
    const int nb = blockIdx.x * 32, kbv = blockIdx.y * 32;
    const int tx = threadIdx.x, ty = threadIdx.y;
#pragma unroll
    for (int j = 0; j < 32; j += 8) s[ty + j][tx] = Wz[(size_t)(kbv + ty + j) * N + nb + tx];
    __syncthreads();
#pragma unroll
    for (int j = 0; j < 32; j += 8) Wtz[(size_t)(nb + ty + j) * K + kbv + tx] = s[tx][ty + j];
}

// ---------------- router final layer: logits -> softmax -> top2 ----------------
__global__ void router_topk(const float* __restrict__ h2,
                            const float* __restrict__ rW3,
                            const float* __restrict__ rb3)
{
    const int warp = (blockIdx.x * blockDim.x + threadIdx.x) >> 5;
    const int lane = threadIdx.x & 31;
    if (warp >= NTOK) return;
    const float* hrow = h2 + (size_t)warp * HH;
    float acc[8] = {0.f, 0.f, 0.f, 0.f, 0.f, 0.f, 0.f, 0.f};
    for (int i = lane; i < HH; i += 32) {
        const float hv = hrow[i];
        const float4 w0 = *(const float4*)(rW3 + (size_t)i * 8);
        const float4 w1 = *(const float4*)(rW3 + (size_t)i * 8 + 4);
        acc[0] += hv * w0.x; acc[1] += hv * w0.y; acc[2] += hv * w0.z; acc[3] += hv * w0.w;
        acc[4] += hv * w1.x; acc[5] += hv * w1.y; acc[6] += hv * w1.z; acc[7] += hv * w1.w;
    }
#pragma unroll
    for (int e = 0; e < 8; ++e)
#pragma unroll
        for (int off = 16; off > 0; off >>= 1)
            acc[e] += __shfl_xor_sync(0xffffffffu, acc[e], off);
    if (lane == 0) {
        float lg[8], mx = -1e30f;
#pragma unroll
        for (int e = 0; e < 8; ++e) { lg[e] = acc[e] + rb3[e]; mx = fmaxf(mx, lg[e]); }
        float sm[8], sum = 0.f;
#pragma unroll
        for (int e = 0; e < 8; ++e) { sm[e] = __expf(lg[e] - mx); sum += sm[e]; }
        const float inv = 1.f / sum;
#pragma unroll
        for (int e = 0; e < 8; ++e) sm[e] *= inv;
        int e1 = 0; float v1 = sm[0];
#pragma unroll
        for (int e = 1; e < 8; ++e) if (sm[e] > v1) { v1 = sm[e]; e1 = e; }
        int e2 = -1; float v2 = -1e30f;
#pragma unroll
        for (int e = 0; e < 8; ++e) {
            if (e == e1) continue;
            if (sm[e] > v2) { v2 = sm[e]; e2 = e; }
        }
        const int j = warp * 2;
        g_expert[j] = e1;     g_gate[j] = v1;
        g_expert[j + 1] = e2; g_gate[j + 1] = v2;
    }
}

// ---------------- per-(b,e) capacity scan (smem-staged) ----------------
__global__ void scan_capacity()
{
    __shared__ int se[TT * 2];
    const int b = blockIdx.x;
    const int base = b * (TT * 2);
    for (int i = threadIdx.x; i < TT * 2; i += blockDim.x) se[i] = g_expert[base + i];
    __syncthreads();
    const int e = threadIdx.x;
    if (e < EE) {
        int cnt = 0;
        for (int i = 0; i < TT * 2; ++i)
            if (se[i] == e) { g_pos[base + i] = (cnt < CAP) ? cnt : -1; ++cnt; }
    }
}

// ---------------- gather kept tokens ----------------
__global__ void scatter_x(const float* __restrict__ x)
{
    const int j = blockIdx.x;
    const int pos = g_pos[j];
    if (pos < 0) return;
    const int e = g_expert[j];
    const int b = j / (TT * 2);
    const int t = (j % (TT * 2)) >> 1;
    const float4* src = (const float4*)(x + (size_t)(b * TT + t) * CC);
    float4* dst = (float4*)(g_xe + ((size_t)e * ROWSE + b * CAP + pos) * CC);
    for (int c = threadIdx.x; c < CC / 4; c += blockDim.x) dst[c] = src[c];
}

// ---------------- combine ----------------
__global__ void combine(float* __restrict__ out)
{
    const int tok = blockIdx.x;
    const int b = tok / TT;
    const int j = tok * 2;
    const int e0 = g_expert[j],     p0 = g_pos[j];     const float w0 = g_gate[j];
    const int e1 = g_expert[j + 1], p1 = g_pos[j + 1]; const float w1 = g_gate[j + 1];
    const float4* y0 = (p0 >= 0) ? (const float4*)(g_ye + ((size_t)e0 * ROWSE + b * CAP + p0) * CC) : nullptr;
    const float4* y1 = (p1 >= 0) ? (const float4*)(g_ye + ((size_t)e1 * ROWSE + b * CAP + p1) * CC) : nullptr;
    float4* o = (float4*)(out + (size_t)tok * CC);
    for (int c = threadIdx.x; c < CC / 4; c += blockDim.x) {
        float4 acc = make_float4(0.f, 0.f, 0.f, 0.f);
        if (y0) { float4 v = y0[c]; acc.x += w0 * v.x; acc.y += w0 * v.y; acc.z += w0 * v.z; acc.w += w0 * v.w; }
        if (y1) { float4 v = y1[c]; acc.x += w1 * v.x; acc.y += w1 * v.y; acc.z += w1 * v.z; acc.w += w1 * v.w; }
        o[c] = acc;
    }
}

// ---------------- launch ----------------
extern "C" void kernel_launch(void* const* d_in, const int* in_sizes, int n_in,
                              void* d_out, int out_size)
{
    const float* x   = (const float*)d_in[0];
    const float* rW1 = (const float*)d_in[1];
    const float* rb1 = (const float*)d_in[2];
    const float* rW2 = (const float*)d_in[3];
    const float* rb2 = (const float*)d_in[4];
    const float* rW3 = (const float*)d_in[5];
    const float* rb3 = (const float*)d_in[6];
    const float* eW1 = (const float*)d_in[7];
    const float* eb1 = (const float*)d_in[8];
    const float* eW2 = (const float*)d_in[9];
    const float* eb2 = (const float*)d_in[10];
    float* out = (float*)d_out;

    float *h1, *h2, *xe, *he, *ye, *rW1t, *rW2t, *eW1t, *eW2t;
    cudaGetSymbolAddress((void**)&h1, g_h1);
    cudaGetSymbolAddress((void**)&h2, g_h2);
    cudaGetSymbolAddress((void**)&xe, g_xe);
    cudaGetSymbolAddress((void**)&he, g_he);
    cudaGetSymbolAddress((void**)&ye, g_ye);
    cudaGetSymbolAddress((void**)&rW1t, g_rW1t);
    cudaGetSymbolAddress((void**)&rW2t, g_rW2t);
    cudaGetSymbolAddress((void**)&eW1t, g_eW1t);
    cudaGetSymbolAddress((void**)&eW2t, g_eW2t);

    const int smemBytes = SMEM_FLOATS * sizeof(float);   // 40 KB
    cudaFuncSetAttribute(mma_gemm<true>,  cudaFuncAttributeMaxDynamicSharedMemorySize, smemBytes);
    cudaFuncSetAttribute(mma_gemm<false>, cudaFuncAttributeMaxDynamicSharedMemorySize, smemBytes);

    // weight transposes: W[K,N] -> Wt[N,K]
    transpose_w<<<dim3(HH / 32, CC / 32, 1),  dim3(32, 8)>>>(rW1, rW1t, CC, HH, 0, 0);
    transpose_w<<<dim3(HH / 32, HH / 32, 1),  dim3(32, 8)>>>(rW2, rW2t, HH, HH, 0, 0);
    transpose_w<<<dim3(HH / 32, CC / 32, EE), dim3(32, 8)>>>(eW1, eW1t, CC, HH,
        (long long)CC * HH, (long long)HH * CC);
    transpose_w<<<dim3(CC / 32, HH / 32, EE), dim3(32, 8)>>>(eW2, eW2t, HH, CC,
        (long long)HH * CC, (long long)CC * HH);

    // router layer 1: h1 = relu(x @ rW1 + rb1)
    mma_gemm<true><<<dim3(HH / 128, NTOK / 128, 1), 256, smemBytes>>>(
        x, rW1t, rb1, h1, HH, CC, 0, 0, 0, 0);
    // router layer 2: h2 = relu(h1 @ rW2 + rb2)
    mma_gemm<true><<<dim3(HH / 128, NTOK / 128, 1), 256, smemBytes>>>(
        h1, rW2t, rb2, h2, HH, HH, 0, 0, 0, 0);
    // logits + softmax + top2
    router_topk<<<(NTOK * 32) / 256, 256>>>(h2, rW3, rb3);
    // capacity positions
    scan_capacity<<<BB, 256>>>();
    // dispatch
    scatter_x<<<NASN, 256>>>(x);
    // expert layer 1: he = relu(xe @ eW1[e] + eb1[e])
    mma_gemm<true><<<dim3(HH / 128, ROWSE / 128, EE), 256, smemBytes>>>(
        xe, eW1t, eb1, he, HH, CC,
        (long long)ROWSE * CC, (long long)HH * CC, HH, (long long)ROWSE * HH);
    // expert layer 2: ye = he @ eW2[e] + eb2[e]
    mma_gemm<false><<<dim3(CC / 128, ROWSE / 128, EE), 256, smemBytes>>>(
        he, eW2t, eb2, ye, CC, HH,
        (long long)ROWSE * HH, (long long)CC * HH, CC, (long long)ROWSE * CC);
    // combine
    combine<<<NTOK, 256>>>(out);
}

// round 6
// speedup vs baseline: 2.3915x; 1.7153x over previous
#include <cuda_runtime.h>
#include <cuda_fp16.h>
#include <cstdint>

// ---------------- problem constants ----------------
#define BB   8
#define TT   2048
#define CC   1024
#define EE   8
#define HH   4096
#define CAP  320
#define NTOK (BB * TT)
#define NASN (NTOK * 2)
#define ROWSE (BB * CAP)          // 2560

// ---------------- scratch (f16 hi/lo storage format) ----------------
static __device__ __half g_xh [(size_t)NTOK * CC],  g_xl [(size_t)NTOK * CC];
static __device__ __half g_h1h[(size_t)NTOK * HH],  g_h1l[(size_t)NTOK * HH];
static __device__ float  g_h2 [(size_t)NTOK * HH];
static __device__ __half g_xeh[(size_t)EE * ROWSE * CC], g_xel[(size_t)EE * ROWSE * CC];
static __device__ __half g_heh[(size_t)EE * ROWSE * HH], g_hel[(size_t)EE * ROWSE * HH];
static __device__ float  g_ye [(size_t)EE * ROWSE * CC];
static __device__ __half g_rW1h[(size_t)HH * CC],      g_rW1l[(size_t)HH * CC];
static __device__ __half g_rW2h[(size_t)HH * HH],      g_rW2l[(size_t)HH * HH];
static __device__ __half g_eW1h[(size_t)EE * HH * CC], g_eW1l[(size_t)EE * HH * CC];
static __device__ __half g_eW2h[(size_t)EE * CC * HH], g_eW2l[(size_t)EE * CC * HH];
static __device__ int    g_expert[NASN];
static __device__ float  g_gate[NASN];
static __device__ int    g_pos[NASN];

// ---------------- helpers ----------------
__device__ __forceinline__ void mma_f16(float* c, const uint32_t* a, uint32_t b0, uint32_t b1) {
    asm("mma.sync.aligned.m16n8k16.row.col.f32.f16.f16.f32 "
        "{%0,%1,%2,%3}, {%4,%5,%6,%7}, {%8,%9}, {%0,%1,%2,%3};"
        : "+f"(c[0]), "+f"(c[1]), "+f"(c[2]), "+f"(c[3])
        : "r"(a[0]), "r"(a[1]), "r"(a[2]), "r"(a[3]), "r"(b0), "r"(b1));
}

// smem tiles: f16, 128 rows x 16 k, padded to 24 halves/row (conflict-free frag LDS)
#define HPAD 24
#define HTILE (128 * HPAD)                 // 3072 halves per tile
#define STAGE_H (4 * HTILE)                // AH, AL, BH, BL
#define SMEM_HALVES (2 * STAGE_H)          // double buffered: 49152 B
#define OFF_AH 0
#define OFF_AL HTILE
#define OFF_BH (2 * HTILE)
#define OFF_BL (3 * HTILE)

// ---------------- 3x/2x FP16 mma.sync GEMM: C = act(A @ Bt^T + bias) ----------------
// A given as f16 hi/lo [M,K]; Bt as f16 hi/lo [N,K]. PASSES=3: AhBh+AhBl+AlBh (~fp32);
// PASSES=2: AhBh+AlBh (B at f16 precision). Output f32 or split f16 hi/lo.
template <int PASSES, bool RELU, bool SPLIT_OUT>
__global__ __launch_bounds__(256, 2)
void hmma_gemm(const __half* __restrict__ Ahg, const __half* __restrict__ Alg,
               const __half* __restrict__ Bhg, const __half* __restrict__ Blg,
               const float* __restrict__ biasg,
               float* __restrict__ Cfg, __half* __restrict__ Chg, __half* __restrict__ Clg,
               int N, int K,
               long long sA, long long sB, long long sBias, long long sC)
{
    extern __shared__ __half sm[];
    const int tid  = threadIdx.x;
    const int wid  = tid >> 5;
    const int lane = tid & 31;
    const int g    = lane >> 2;
    const int q    = lane & 3;

    const size_t aBase = blockIdx.z * sA + (size_t)blockIdx.y * 128 * K;
    const size_t bBase = blockIdx.z * sB + (size_t)blockIdx.x * 128 * K;
    const float* bias  = biasg + blockIdx.z * sBias + blockIdx.x * 128;
    const size_t cBase = blockIdx.z * sC + (size_t)blockIdx.y * 128 * N + blockIdx.x * 128;

    const int wm = (wid & 3) * 32;      // warp tile 32x64
    const int wn = (wid >> 2) * 64;

    // loader: row = tid>>1 (0..127), kb = (tid&1)*8 halves
    const int row = tid >> 1;
    const int kb  = (tid & 1) << 3;
    const __half* pAh = Ahg + aBase + (size_t)row * K + kb;
    const __half* pAl = Alg + aBase + (size_t)row * K + kb;
    const __half* pBh = Bhg + bBase + (size_t)row * K + kb;
    const __half* pBl = (PASSES == 3) ? (Blg + bBase + (size_t)row * K + kb) : nullptr;
    const int sts = row * HPAD + kb;

    float acc[2][8][4];
#pragma unroll
    for (int mt = 0; mt < 2; ++mt)
#pragma unroll
        for (int nt = 0; nt < 8; ++nt)
#pragma unroll
            for (int i = 0; i < 4; ++i) acc[mt][nt][i] = 0.f;

    const int T = K >> 4;

    uint4 rAh = *(const uint4*)pAh;
    uint4 rAl = *(const uint4*)pAl;
    uint4 rBh = *(const uint4*)pBh;
    uint4 rBl = (PASSES == 3) ? *(const uint4*)pBl : make_uint4(0, 0, 0, 0);
    *(uint4*)(sm + OFF_AH + sts) = rAh;
    *(uint4*)(sm + OFF_AL + sts) = rAl;
    *(uint4*)(sm + OFF_BH + sts) = rBh;
    if (PASSES == 3) *(uint4*)(sm + OFF_BL + sts) = rBl;
    __syncthreads();

    for (int t = 0; t < T; ++t) {
        const bool more = (t + 1 < T);
        if (more) {
            const int o = (t + 1) << 4;
            rAh = *(const uint4*)(pAh + o);
            rAl = *(const uint4*)(pAl + o);
            rBh = *(const uint4*)(pBh + o);
            if (PASSES == 3) rBl = *(const uint4*)(pBl + o);
        }

        const __half* st = sm + (t & 1) * STAGE_H;
        const __half* sAH = st + OFF_AH;
        const __half* sAL = st + OFF_AL;
        const __half* sBH = st + OFF_BH;
        const __half* sBL = st + OFF_BL;

        uint32_t ah[2][4], al[2][4];
#pragma unroll
        for (int mt = 0; mt < 2; ++mt) {
            const int i0 = (wm + 16 * mt + g) * HPAD + 2 * q;
            ah[mt][0] = *(const uint32_t*)(sAH + i0);
            ah[mt][1] = *(const uint32_t*)(sAH + i0 + 8 * HPAD);
            ah[mt][2] = *(const uint32_t*)(sAH + i0 + 8);
            ah[mt][3] = *(const uint32_t*)(sAH + i0 + 8 * HPAD + 8);
            al[mt][0] = *(const uint32_t*)(sAL + i0);
            al[mt][1] = *(const uint32_t*)(sAL + i0 + 8 * HPAD);
            al[mt][2] = *(const uint32_t*)(sAL + i0 + 8);
            al[mt][3] = *(const uint32_t*)(sAL + i0 + 8 * HPAD + 8);
        }
#pragma unroll
        for (int nt = 0; nt < 8; ++nt) {
            const int j0 = (wn + 8 * nt + g) * HPAD + 2 * q;
            const uint32_t bh0 = *(const uint32_t*)(sBH + j0);
            const uint32_t bh1 = *(const uint32_t*)(sBH + j0 + 8);
            uint32_t bl0 = 0, bl1 = 0;
            if (PASSES == 3) {
                bl0 = *(const uint32_t*)(sBL + j0);
                bl1 = *(const uint32_t*)(sBL + j0 + 8);
            }
#pragma unroll
            for (int mt = 0; mt < 2; ++mt) {
                mma_f16(acc[mt][nt], ah[mt], bh0, bh1);
                mma_f16(acc[mt][nt], al[mt], bh0, bh1);
                if (PASSES == 3) mma_f16(acc[mt][nt], ah[mt], bl0, bl1);
            }
        }

        if (more) {
            __half* dst = sm + ((t + 1) & 1) * STAGE_H;
            *(uint4*)(dst + OFF_AH + sts) = rAh;
            *(uint4*)(dst + OFF_AL + sts) = rAl;
            *(uint4*)(dst + OFF_BH + sts) = rBh;
            if (PASSES == 3) *(uint4*)(dst + OFF_BL + sts) = rBl;
        }
        __syncthreads();
    }

    // epilogue
#pragma unroll
    for (int nt = 0; nt < 8; ++nt) {
        const int c = wn + 8 * nt + 2 * q;
        const float b0 = bias[c], b1 = bias[c + 1];
#pragma unroll
        for (int mt = 0; mt < 2; ++mt) {
            const int r = wm + 16 * mt + g;
            float2 v0, v1;
            v0.x = acc[mt][nt][0] + b0; v0.y = acc[mt][nt][1] + b1;
            v1.x = acc[mt][nt][2] + b0; v1.y = acc[mt][nt][3] + b1;
            if (RELU) {
                v0.x = fmaxf(v0.x, 0.f); v0.y = fmaxf(v0.y, 0.f);
                v1.x = fmaxf(v1.x, 0.f); v1.y = fmaxf(v1.y, 0.f);
            }
            if (SPLIT_OUT) {
                __half2 h0 = __floats2half2_rn(v0.x, v0.y);
                __half2 h1 = __floats2half2_rn(v1.x, v1.y);
                float2 f0 = __half22float2(h0);
                float2 f1 = __half22float2(h1);
                __half2 l0 = __floats2half2_rn(v0.x - f0.x, v0.y - f0.y);
                __half2 l1 = __floats2half2_rn(v1.x - f1.x, v1.y - f1.y);
                *(__half2*)(Chg + cBase + (size_t)r * N + c)       = h0;
                *(__half2*)(Clg + cBase + (size_t)r * N + c)       = l0;
                *(__half2*)(Chg + cBase + (size_t)(r + 8) * N + c) = h1;
                *(__half2*)(Clg + cBase + (size_t)(r + 8) * N + c) = l1;
            } else {
                *(float2*)(Cfg + cBase + (size_t)r * N + c)       = v0;
                *(float2*)(Cfg + cBase + (size_t)(r + 8) * N + c) = v1;
            }
        }
    }
}

// ---------------- split fp32 -> f16 hi/lo ----------------
__global__ void split_f32(const float* __restrict__ in, __half* __restrict__ hi,
                          __half* __restrict__ lo, size_t n)
{
    const size_t i = ((size_t)blockIdx.x * blockDim.x + threadIdx.x) * 4;
    if (i >= n) return;
    const float4 v = *(const float4*)(in + i);
    __half2 h0 = __floats2half2_rn(v.x, v.y);
    __half2 h1 = __floats2half2_rn(v.z, v.w);
    float2 f0 = __half22float2(h0);
    float2 f1 = __half22float2(h1);
    __half2 l0 = __floats2half2_rn(v.x - f0.x, v.y - f0.y);
    __half2 l1 = __floats2half2_rn(v.z - f1.x, v.w - f1.y);
    *(__half2*)(hi + i)     = h0;
    *(__half2*)(hi + i + 2) = h1;
    *(__half2*)(lo + i)     = l0;
    *(__half2*)(lo + i + 2) = l1;
}

// ---------------- weight transpose + split: W [K,N] f32 -> Wt hi/lo [N,K] f16 ----------------
__global__ void transpose_split_w(const float* __restrict__ W,
                                  __half* __restrict__ Wth, __half* __restrict__ Wtl,
                                  int K, int N, long long sIn, long long sOut)
{
    __shared__ float s[32][33];
    const float* Wz = W + blockIdx.z * sIn;
    __half* Wh = Wth + blockIdx.z * sOut;
    __half* Wl = Wtl + blockIdx.z * sOut;
    const int nb = blockIdx.x * 32, kbv = blockIdx.y * 32;
    const int tx = threadIdx.x, ty = threadIdx.y;
#pragma unroll
    for (int j = 0; j < 32; j += 8) s[ty + j][tx] = Wz[(size_t)(kbv + ty + j) * N + nb + tx];
    __syncthreads();
#pragma unroll
    for (int j = 0; j < 32; j += 8) {
        const float v = s[tx][ty + j];
        const __half h = __float2half_rn(v);
        Wh[(size_t)(nb + ty + j) * K + kbv + tx] = h;
        Wl[(size_t)(nb + ty + j) * K + kbv + tx] = __float2half_rn(v - __half2float(h));
    }
}

// ---------------- router final layer ----------------
__global__ void router_topk(const float* __restrict__ h2,
                            const float* __restrict__ rW3,
                            const float* __restrict__ rb3)
{
    const int warp = (blockIdx.x * blockDim.x + threadIdx.x) >> 5;
    const int lane = threadIdx.x & 31;
    if (warp >= NTOK) return;
    const float* hrow = h2 + (size_t)warp * HH;
    float acc[8] = {0.f, 0.f, 0.f, 0.f, 0.f, 0.f, 0.f, 0.f};
    for (int i = lane; i < HH; i += 32) {
        const float hv = hrow[i];
        const float4 w0 = *(const float4*)(rW3 + (size_t)i * 8);
        const float4 w1 = *(const float4*)(rW3 + (size_t)i * 8 + 4);
        acc[0] += hv * w0.x; acc[1] += hv * w0.y; acc[2] += hv * w0.z; acc[3] += hv * w0.w;
        acc[4] += hv * w1.x; acc[5] += hv * w1.y; acc[6] += hv * w1.z; acc[7] += hv * w1.w;
    }
#pragma unroll
    for (int e = 0; e < 8; ++e)
#pragma unroll
        for (int off = 16; off > 0; off >>= 1)
            acc[e] += __shfl_xor_sync(0xffffffffu, acc[e], off);
    if (lane == 0) {
        float lg[8], mx = -1e30f;
#pragma unroll
        for (int e = 0; e < 8; ++e) { lg[e] = acc[e] + rb3[e]; mx = fmaxf(mx, lg[e]); }
        float sm[8], sum = 0.f;
#pragma unroll
        for (int e = 0; e < 8; ++e) { sm[e] = __expf(lg[e] - mx); sum += sm[e]; }
        const float inv = 1.f / sum;
#pragma unroll
        for (int e = 0; e < 8; ++e) sm[e] *= inv;
        int e1 = 0; float v1 = sm[0];
#pragma unroll
        for (int e = 1; e < 8; ++e) if (sm[e] > v1) { v1 = sm[e]; e1 = e; }
        int e2 = -1; float v2 = -1e30f;
#pragma unroll
        for (int e = 0; e < 8; ++e) {
            if (e == e1) continue;
            if (sm[e] > v2) { v2 = sm[e]; e2 = e; }
        }
        const int j = warp * 2;
        g_expert[j] = e1;     g_gate[j] = v1;
        g_expert[j + 1] = e2; g_gate[j + 1] = v2;
    }
}

// ---------------- per-(b,e) capacity scan ----------------
__global__ void scan_capacity()
{
    __shared__ int se[TT * 2];
    const int b = blockIdx.x;
    const int base = b * (TT * 2);
    for (int i = threadIdx.x; i < TT * 2; i += blockDim.x) se[i] = g_expert[base + i];
    __syncthreads();
    const int e = threadIdx.x;
    if (e < EE) {
        int cnt = 0;
        for (int i = 0; i < TT * 2; ++i)
            if (se[i] == e) { g_pos[base + i] = (cnt < CAP) ? cnt : -1; ++cnt; }
    }
}

// ---------------- gather kept tokens (copy split f16 rows) ----------------
__global__ void scatter_x()
{
    const int j = blockIdx.x;
    const int pos = g_pos[j];
    if (pos < 0) return;
    const int e = g_expert[j];
    const int b = j / (TT * 2);
    const int t = (j % (TT * 2)) >> 1;
    const size_t srcOff = (size_t)(b * TT + t) * CC;
    const size_t dstOff = ((size_t)e * ROWSE + b * CAP + pos) * CC;
    const uint4* sh = (const uint4*)(g_xh + srcOff);
    const uint4* sl = (const uint4*)(g_xl + srcOff);
    uint4* dh = (uint4*)(g_xeh + dstOff);
    uint4* dl = (uint4*)(g_xel + dstOff);
    for (int c = threadIdx.x; c < CC / 8; c += blockDim.x) { dh[c] = sh[c]; dl[c] = sl[c]; }
}

// ---------------- combine ----------------
__global__ void combine(float* __restrict__ out)
{
    const int tok = blockIdx.x;
    const int b = tok / TT;
    const int j = tok * 2;
    const int e0 = g_expert[j],     p0 = g_pos[j];     const float w0 = g_gate[j];
    const int e1 = g_expert[j + 1], p1 = g_pos[j + 1]; const float w1 = g_gate[j + 1];
    const float4* y0 = (p0 >= 0) ? (const float4*)(g_ye + ((size_t)e0 * ROWSE + b * CAP + p0) * CC) : nullptr;
    const float4* y1 = (p1 >= 0) ? (const float4*)(g_ye + ((size_t)e1 * ROWSE + b * CAP + p1) * CC) : nullptr;
    float4* o = (float4*)(out + (size_t)tok * CC);
    for (int c = threadIdx.x; c < CC / 4; c += blockDim.x) {
        float4 acc = make_float4(0.f, 0.f, 0.f, 0.f);
        if (y0) { float4 v = y0[c]; acc.x += w0 * v.x; acc.y += w0 * v.y; acc.z += w0 * v.z; acc.w += w0 * v.w; }
        if (y1) { float4 v = y1[c]; acc.x += w1 * v.x; acc.y += w1 * v.y; acc.z += w1 * v.z; acc.w += w1 * v.w; }
        o[c] = acc;
    }
}

// ---------------- launch ----------------
extern "C" void kernel_launch(void* const* d_in, const int* in_sizes, int n_in,
                              void* d_out, int out_size)
{
    const float* x   = (const float*)d_in[0];
    const float* rW1 = (const float*)d_in[1];
    const float* rb1 = (const float*)d_in[2];
    const float* rW2 = (const float*)d_in[3];
    const float* rb2 = (const float*)d_in[4];
    const float* rW3 = (const float*)d_in[5];
    const float* rb3 = (const float*)d_in[6];
    const float* eW1 = (const float*)d_in[7];
    const float* eb1 = (const float*)d_in[8];
    const float* eW2 = (const float*)d_in[9];
    const float* eb2 = (const float*)d_in[10];
    float* out = (float*)d_out;

    __half *xh, *xl, *h1h, *h1l, *xeh, *xel, *heh, *hel;
    __half *rW1h, *rW1l, *rW2h, *rW2l, *eW1h, *eW1l, *eW2h, *eW2l;
    float *h2, *ye;
    cudaGetSymbolAddress((void**)&xh, g_xh);   cudaGetSymbolAddress((void**)&xl, g_xl);
    cudaGetSymbolAddress((void**)&h1h, g_h1h); cudaGetSymbolAddress((void**)&h1l, g_h1l);
    cudaGetSymbolAddress((void**)&h2, g_h2);
    cudaGetSymbolAddress((void**)&xeh, g_xeh); cudaGetSymbolAddress((void**)&xel, g_xel);
    cudaGetSymbolAddress((void**)&heh, g_heh); cudaGetSymbolAddress((void**)&hel, g_hel);
    cudaGetSymbolAddress((void**)&ye, g_ye);
    cudaGetSymbolAddress((void**)&rW1h, g_rW1h); cudaGetSymbolAddress((void**)&rW1l, g_rW1l);
    cudaGetSymbolAddress((void**)&rW2h, g_rW2h); cudaGetSymbolAddress((void**)&rW2l, g_rW2l);
    cudaGetSymbolAddress((void**)&eW1h, g_eW1h); cudaGetSymbolAddress((void**)&eW1l, g_eW1l);
    cudaGetSymbolAddress((void**)&eW2h, g_eW2h); cudaGetSymbolAddress((void**)&eW2l, g_eW2l);

    const int smemBytes = SMEM_HALVES * sizeof(__half);   // 48 KB
    cudaFuncSetAttribute(hmma_gemm<3, true,  true >, cudaFuncAttributeMaxDynamicSharedMemorySize, smemBytes);
    cudaFuncSetAttribute(hmma_gemm<3, true,  false>, cudaFuncAttributeMaxDynamicSharedMemorySize, smemBytes);
    cudaFuncSetAttribute(hmma_gemm<2, true,  true >, cudaFuncAttributeMaxDynamicSharedMemorySize, smemBytes);
    cudaFuncSetAttribute(hmma_gemm<2, false, false>, cudaFuncAttributeMaxDynamicSharedMemorySize, smemBytes);

    // input split + weight transpose/split
    split_f32<<<(NTOK * CC / 4 + 255) / 256, 256>>>(x, xh, xl, (size_t)NTOK * CC);
    transpose_split_w<<<dim3(HH / 32, CC / 32, 1),  dim3(32, 8)>>>(rW1, rW1h, rW1l, CC, HH, 0, 0);
    transpose_split_w<<<dim3(HH / 32, HH / 32, 1),  dim3(32, 8)>>>(rW2, rW2h, rW2l, HH, HH, 0, 0);
    transpose_split_w<<<dim3(HH / 32, CC / 32, EE), dim3(32, 8)>>>(eW1, eW1h, eW1l, CC, HH,
        (long long)CC * HH, (long long)HH * CC);
    transpose_split_w<<<dim3(CC / 32, HH / 32, EE), dim3(32, 8)>>>(eW2, eW2h, eW2l, HH, CC,
        (long long)HH * CC, (long long)CC * HH);

    // router layer 1: h1 = relu(x @ rW1 + rb1)  (split output)
    hmma_gemm<3, true, true><<<dim3(HH / 128, NTOK / 128, 1), 256, smemBytes>>>(
        xh, xl, rW1h, rW1l, rb1, nullptr, h1h, h1l, HH, CC, 0, 0, 0, 0);
    // router layer 2: h2 = relu(h1 @ rW2 + rb2)  (f32 output)
    hmma_gemm<3, true, false><<<dim3(HH / 128, NTOK / 128, 1), 256, smemBytes>>>(
        h1h, h1l, rW2h, rW2l, rb2, h2, nullptr, nullptr, HH, HH, 0, 0, 0, 0);
    // logits + softmax + top2
    router_topk<<<(NTOK * 32) / 256, 256>>>(h2, rW3, rb3);
    // capacity positions
    scan_capacity<<<BB, 256>>>();
    // dispatch (split rows)
    scatter_x<<<NASN, 128>>>();
    // expert layer 1: he = relu(xe @ eW1[e] + eb1[e])  (2-pass, split output)
    hmma_gemm<2, true, true><<<dim3(HH / 128, ROWSE / 128, EE), 256, smemBytes>>>(
        xeh, xel, eW1h, eW1l, eb1, nullptr, heh, hel, HH, CC,
        (long long)ROWSE * CC, (long long)HH * CC, HH, (long long)ROWSE * HH);
    // expert layer 2: ye = he @ eW2[e] + eb2[e]  (2-pass, f32 output)
    hmma_gemm<2, false, false><<<dim3(CC / 128, ROWSE / 128, EE), 256, smemBytes>>>(
        heh, hel, eW2h, eW2l, eb2, ye, nullptr, nullptr, CC, HH,
        (long long)ROWSE * HH, (long long)CC * HH, CC, (long long)ROWSE * CC);
    // combine
    combine<<<NTOK, 256>>>(out);
}

// round 7
// speedup vs baseline: 2.9231x; 1.2223x over previous
#include <cuda_runtime.h>
#include <cuda_fp16.h>
#include <cstdint>

// ---------------- problem constants ----------------
#define BB   8
#define TT   2048
#define CC   1024
#define EE   8
#define HH   4096
#define CAP  320
#define NTOK (BB * TT)
#define NASN (NTOK * 2)
#define ROWSE (BB * CAP)          // 2560

// ---------------- scratch ----------------
static __device__ __half g_xh [(size_t)NTOK * CC],  g_xl [(size_t)NTOK * CC];
static __device__ __half g_h1h[(size_t)NTOK * HH],  g_h1l[(size_t)NTOK * HH];
static __device__ float  g_h2 [(size_t)NTOK * HH];
static __device__ __half g_xeh[(size_t)EE * ROWSE * CC];
static __device__ __half g_heh[(size_t)EE * ROWSE * HH];
static __device__ float  g_ye [(size_t)EE * ROWSE * CC];
static __device__ __half g_rW1h[(size_t)HH * CC],      g_rW1l[(size_t)HH * CC];
static __device__ __half g_rW2h[(size_t)HH * HH],      g_rW2l[(size_t)HH * HH];
static __device__ __half g_eW1h[(size_t)EE * HH * CC];
static __device__ __half g_eW2h[(size_t)EE * CC * HH];
static __device__ int    g_expert[NASN];
static __device__ float  g_gate[NASN];
static __device__ int    g_pos[NASN];

// ---------------- helpers ----------------
__device__ __forceinline__ uint32_t smem_u32(const void* p) {
    uint32_t a;
    asm("{ .reg .u64 t; cvta.to.shared.u64 t, %1; cvt.u32.u64 %0, t; }" : "=r"(a) : "l"(p));
    return a;
}
__device__ __forceinline__ void mma_f16(float* c, const uint32_t* a, uint32_t b0, uint32_t b1) {
    asm("mma.sync.aligned.m16n8k16.row.col.f32.f16.f16.f32 "
        "{%0,%1,%2,%3}, {%4,%5,%6,%7}, {%8,%9}, {%0,%1,%2,%3};"
        : "+f"(c[0]), "+f"(c[1]), "+f"(c[2]), "+f"(c[3])
        : "r"(a[0]), "r"(a[1]), "r"(a[2]), "r"(a[3]), "r"(b0), "r"(b1));
}
#define LDMX4(R, ADDR) \
    asm volatile("ldmatrix.sync.aligned.m8n8.x4.shared.b16 {%0,%1,%2,%3}, [%4];" \
        : "=r"((R)[0]), "=r"((R)[1]), "=r"((R)[2]), "=r"((R)[3]) : "r"(ADDR))

// smem tiles: f16, 128 rows x 16 k, padded to 40 halves/row.
// 80B row stride: 16B-aligned rows (ldmatrix requirement), stride-20-words is
// conflict-free across the 8 rows of an ldmatrix phase.
#define HPAD 40
#define HTILE (128 * HPAD)                 // halves per tile
#define OFF_AH 0
#define OFF_AL HTILE                       // only PASSES==3
// BH offset depends on PASSES (packed for 1-pass); see template body.

// ---------------- FP16 mma.sync GEMM with ldmatrix: C = act(A @ Bt^T + bias) ----------------
// A f16 hi(/lo) [M,K]; Bt f16 hi(/lo) [N,K].
// PASSES=3: AhBh+AlBh+AhBl (~fp32);  PASSES=1: AhBh (f16).
// OUT: 0 = f32, 1 = split f16 hi/lo, 2 = f16 hi only.
template <int PASSES, bool RELU, int OUT>
__global__ __launch_bounds__(256, 2)
void hmma_gemm(const __half* __restrict__ Ahg, const __half* __restrict__ Alg,
               const __half* __restrict__ Bhg, const __half* __restrict__ Blg,
               const float* __restrict__ biasg,
               float* __restrict__ Cfg, __half* __restrict__ Chg, __half* __restrict__ Clg,
               int N, int K,
               long long sA, long long sB, long long sBias, long long sC)
{
    constexpr int NT_TILES = (PASSES == 3) ? 4 : 2;
    constexpr int OFF_BH = (PASSES == 3) ? 2 * HTILE : HTILE;
    constexpr int OFF_BL = 3 * HTILE;      // only PASSES==3
    constexpr int STAGE_H = NT_TILES * HTILE;

    extern __shared__ __half sm[];
    const uint32_t sb = smem_u32(sm);
    const int tid  = threadIdx.x;
    const int wid  = tid >> 5;
    const int lane = tid & 31;
    const int q    = lane & 3;

    const size_t aBase = blockIdx.z * sA + (size_t)blockIdx.y * 128 * K;
    const size_t bBase = blockIdx.z * sB + (size_t)blockIdx.x * 128 * K;
    const float* bias  = biasg + blockIdx.z * sBias + blockIdx.x * 128;
    const size_t cBase = blockIdx.z * sC + (size_t)blockIdx.y * 128 * N + blockIdx.x * 128;

    const int wm = (wid & 3) * 32;      // warp tile 32x64
    const int wn = (wid >> 2) * 64;

    // ldmatrix per-lane offsets (halves). r = row-in-matrix, s0/s1 select sub-matrix.
    const int r  = lane & 7;
    const int s0 = (lane >> 3) & 1;
    const int s1 = lane >> 4;
    const uint32_t aoff0 = (uint32_t)((wm + r + (s0 << 3)) * HPAD + (s1 << 3));
    const uint32_t aoff1 = aoff0 + 16 * HPAD;
    uint32_t boff[4];
#pragma unroll
    for (int p = 0; p < 4; ++p)
        boff[p] = (uint32_t)((wn + 16 * p + r + (s1 << 3)) * HPAD + (s0 << 3));

    // loader mapping: row = tid>>1, kb = (tid&1)*8 halves
    const int lrow = tid >> 1;
    const int lkb  = (tid & 1) << 3;
    const __half* pAh = Ahg + aBase + (size_t)lrow * K + lkb;
    const __half* pBh = Bhg + bBase + (size_t)lrow * K + lkb;
    const __half* pAl = (PASSES == 3) ? (Alg + aBase + (size_t)lrow * K + lkb) : nullptr;
    const __half* pBl = (PASSES == 3) ? (Blg + bBase + (size_t)lrow * K + lkb) : nullptr;
    const int sts = lrow * HPAD + lkb;

    float acc[2][8][4];
#pragma unroll
    for (int mt = 0; mt < 2; ++mt)
#pragma unroll
        for (int nt = 0; nt < 8; ++nt)
#pragma unroll
            for (int i = 0; i < 4; ++i) acc[mt][nt][i] = 0.f;

    const int T = K >> 4;

    uint4 rAh = *(const uint4*)pAh;
    uint4 rBh = *(const uint4*)pBh;
    uint4 rAl, rBl;
    if (PASSES == 3) { rAl = *(const uint4*)pAl; rBl = *(const uint4*)pBl; }
    *(uint4*)(sm + OFF_AH + sts) = rAh;
    *(uint4*)(sm + OFF_BH + sts) = rBh;
    if (PASSES == 3) {
        *(uint4*)(sm + OFF_AL + sts) = rAl;
        *(uint4*)(sm + OFF_BL + sts) = rBl;
    }
    __syncthreads();

    for (int t = 0; t < T; ++t) {
        const bool more = (t + 1 < T);
        if (more) {
            const int o = (t + 1) << 4;
            rAh = *(const uint4*)(pAh + o);
            rBh = *(const uint4*)(pBh + o);
            if (PASSES == 3) { rAl = *(const uint4*)(pAl + o); rBl = *(const uint4*)(pBl + o); }
        }

        const uint32_t stage = sb + (uint32_t)(((t & 1) ? STAGE_H : 0) * 2);

        uint32_t ah0[4], ah1[4], al0[4], al1[4];
        LDMX4(ah0, stage + (OFF_AH + aoff0) * 2);
        LDMX4(ah1, stage + (OFF_AH + aoff1) * 2);
        if (PASSES == 3) {
            LDMX4(al0, stage + (OFF_AL + aoff0) * 2);
            LDMX4(al1, stage + (OFF_AL + aoff1) * 2);
        }
#pragma unroll
        for (int p = 0; p < 4; ++p) {
            uint32_t bh[4], bl[4];
            LDMX4(bh, stage + (OFF_BH + boff[p]) * 2);
            if (PASSES == 3) LDMX4(bl, stage + (OFF_BL + boff[p]) * 2);
#pragma unroll
            for (int sub = 0; sub < 2; ++sub) {
                const int nt = 2 * p + sub;
                const uint32_t b0 = bh[2 * sub], b1 = bh[2 * sub + 1];
                mma_f16(acc[0][nt], ah0, b0, b1);
                mma_f16(acc[1][nt], ah1, b0, b1);
                if (PASSES == 3) {
                    mma_f16(acc[0][nt], al0, b0, b1);
                    mma_f16(acc[1][nt], al1, b0, b1);
                    mma_f16(acc[0][nt], ah0, bl[2 * sub], bl[2 * sub + 1]);
                    mma_f16(acc[1][nt], ah1, bl[2 * sub], bl[2 * sub + 1]);
                }
            }
        }

        if (more) {
            __half* dst = sm + ((t + 1) & 1) * STAGE_H;
            *(uint4*)(dst + OFF_AH + sts) = rAh;
            *(uint4*)(dst + OFF_BH + sts) = rBh;
            if (PASSES == 3) {
                *(uint4*)(dst + OFF_AL + sts) = rAl;
                *(uint4*)(dst + OFF_BL + sts) = rBl;
            }
        }
        __syncthreads();
    }

    // epilogue: c0/c1 at (row=wm+16mt+g, col 2q, 2q+1); c2/c3 at row+8
    const int gg = lane >> 2;
#pragma unroll
    for (int nt = 0; nt < 8; ++nt) {
        const int c = wn + 8 * nt + 2 * q;
        const float b0 = bias[c], b1 = bias[c + 1];
#pragma unroll
        for (int mt = 0; mt < 2; ++mt) {
            const int rr = wm + 16 * mt + gg;
            float2 v0, v1;
            v0.x = acc[mt][nt][0] + b0; v0.y = acc[mt][nt][1] + b1;
            v1.x = acc[mt][nt][2] + b0; v1.y = acc[mt][nt][3] + b1;
            if (RELU) {
                v0.x = fmaxf(v0.x, 0.f); v0.y = fmaxf(v0.y, 0.f);
                v1.x = fmaxf(v1.x, 0.f); v1.y = fmaxf(v1.y, 0.f);
            }
            if (OUT == 0) {
                *(float2*)(Cfg + cBase + (size_t)rr * N + c)       = v0;
                *(float2*)(Cfg + cBase + (size_t)(rr + 8) * N + c) = v1;
            } else {
                __half2 h0 = __floats2half2_rn(v0.x, v0.y);
                __half2 h1 = __floats2half2_rn(v1.x, v1.y);
                *(__half2*)(Chg + cBase + (size_t)rr * N + c)       = h0;
                *(__half2*)(Chg + cBase + (size_t)(rr + 8) * N + c) = h1;
                if (OUT == 1) {
                    float2 f0 = __half22float2(h0);
                    float2 f1 = __half22float2(h1);
                    __half2 l0 = __floats2half2_rn(v0.x - f0.x, v0.y - f0.y);
                    __half2 l1 = __floats2half2_rn(v1.x - f1.x, v1.y - f1.y);
                    *(__half2*)(Clg + cBase + (size_t)rr * N + c)       = l0;
                    *(__half2*)(Clg + cBase + (size_t)(rr + 8) * N + c) = l1;
                }
            }
        }
    }
}

// ---------------- split fp32 -> f16 hi/lo ----------------
__global__ void split_f32(const float* __restrict__ in, __half* __restrict__ hi,
                          __half* __restrict__ lo, size_t n)
{
    const size_t i = ((size_t)blockIdx.x * blockDim.x + threadIdx.x) * 4;
    if (i >= n) return;
    const float4 v = *(const float4*)(in + i);
    __half2 h0 = __floats2half2_rn(v.x, v.y);
    __half2 h1 = __floats2half2_rn(v.z, v.w);
    float2 f0 = __half22float2(h0);
    float2 f1 = __half22float2(h1);
    __half2 l0 = __floats2half2_rn(v.x - f0.x, v.y - f0.y);
    __half2 l1 = __floats2half2_rn(v.z - f1.x, v.w - f1.y);
    *(__half2*)(hi + i)     = h0;
    *(__half2*)(hi + i + 2) = h1;
    *(__half2*)(lo + i)     = l0;
    *(__half2*)(lo + i + 2) = l1;
}

// ---------------- weight transpose + split: W [K,N] f32 -> Wt hi(/lo) [N,K] f16 ----------------
__global__ void transpose_split_w(const float* __restrict__ W,
                                  __half* __restrict__ Wth, __half* __restrict__ Wtl,
                                  int K, int N, long long sIn, long long sOut)
{
    __shared__ float s[32][33];
    const float* Wz = W + blockIdx.z * sIn;
    __half* Wh = Wth + blockIdx.z * sOut;
    __half* Wl = Wtl ? (Wtl + blockIdx.z * sOut) : nullptr;
    const int nb = blockIdx.x * 32, kbv = blockIdx.y * 32;
    const int tx = threadIdx.x, ty = threadIdx.y;
#pragma unroll
    for (int j = 0; j < 32; j += 8) s[ty + j][tx] = Wz[(size_t)(kbv + ty + j) * N + nb + tx];
    __syncthreads();
#pragma unroll
    for (int j = 0; j < 32; j += 8) {
        const float v = s[tx][ty + j];
        const __half h = __float2half_rn(v);
        Wh[(size_t)(nb + ty + j) * K + kbv + tx] = h;
        if (Wl) Wl[(size_t)(nb + ty + j) * K + kbv + tx] = __float2half_rn(v - __half2float(h));
    }
}

// ---------------- router final layer ----------------
__global__ void router_topk(const float* __restrict__ h2,
                            const float* __restrict__ rW3,
                            const float* __restrict__ rb3)
{
    const int warp = (blockIdx.x * blockDim.x + threadIdx.x) >> 5;
    const int lane = threadIdx.x & 31;
    if (warp >= NTOK) return;
    const float* hrow = h2 + (size_t)warp * HH;
    float acc[8] = {0.f, 0.f, 0.f, 0.f, 0.f, 0.f, 0.f, 0.f};
    for (int i = lane; i < HH; i += 32) {
        const float hv = hrow[i];
        const float4 w0 = *(const float4*)(rW3 + (size_t)i * 8);
        const float4 w1 = *(const float4*)(rW3 + (size_t)i * 8 + 4);
        acc[0] += hv * w0.x; acc[1] += hv * w0.y; acc[2] += hv * w0.z; acc[3] += hv * w0.w;
        acc[4] += hv * w1.x; acc[5] += hv * w1.y; acc[6] += hv * w1.z; acc[7] += hv * w1.w;
    }
#pragma unroll
    for (int e = 0; e < 8; ++e)
#pragma unroll
        for (int off = 16; off > 0; off >>= 1)
            acc[e] += __shfl_xor_sync(0xffffffffu, acc[e], off);
    if (lane == 0) {
        float lg[8], mx = -1e30f;
#pragma unroll
        for (int e = 0; e < 8; ++e) { lg[e] = acc[e] + rb3[e]; mx = fmaxf(mx, lg[e]); }
        float sm[8], sum = 0.f;
#pragma unroll
        for (int e = 0; e < 8; ++e) { sm[e] = __expf(lg[e] - mx); sum += sm[e]; }
        const float inv = 1.f / sum;
#pragma unroll
        for (int e = 0; e < 8; ++e) sm[e] *= inv;
        int e1 = 0; float v1 = sm[0];
#pragma unroll
        for (int e = 1; e < 8; ++e) if (sm[e] > v1) { v1 = sm[e]; e1 = e; }
        int e2 = -1; float v2 = -1e30f;
#pragma unroll
        for (int e = 0; e < 8; ++e) {
            if (e == e1) continue;
            if (sm[e] > v2) { v2 = sm[e]; e2 = e; }
        }
        const int j = warp * 2;
        g_expert[j] = e1;     g_gate[j] = v1;
        g_expert[j + 1] = e2; g_gate[j + 1] = v2;
    }
}

// ---------------- per-(b,e) capacity scan ----------------
__global__ void scan_capacity()
{
    __shared__ int se[TT * 2];
    const int b = blockIdx.x;
    const int base = b * (TT * 2);
    for (int i = threadIdx.x; i < TT * 2; i += blockDim.x) se[i] = g_expert[base + i];
    __syncthreads();
    const int e = threadIdx.x;
    if (e < EE) {
        int cnt = 0;
        for (int i = 0; i < TT * 2; ++i)
            if (se[i] == e) { g_pos[base + i] = (cnt < CAP) ? cnt : -1; ++cnt; }
    }
}

// ---------------- gather kept tokens (f16 hi rows) ----------------
__global__ void scatter_x()
{
    const int j = blockIdx.x;
    const int pos = g_pos[j];
    if (pos < 0) return;
    const int e = g_expert[j];
    const int b = j / (TT * 2);
    const int t = (j % (TT * 2)) >> 1;
    const uint4* sh = (const uint4*)(g_xh + (size_t)(b * TT + t) * CC);
    uint4* dh = (uint4*)(g_xeh + ((size_t)e * ROWSE + b * CAP + pos) * CC);
    for (int c = threadIdx.x; c < CC / 8; c += blockDim.x) dh[c] = sh[c];
}

// ---------------- combine ----------------
__global__ void combine(float* __restrict__ out)
{
    const int tok = blockIdx.x;
    const int b = tok / TT;
    const int j = tok * 2;
    const int e0 = g_expert[j],     p0 = g_pos[j];     const float w0 = g_gate[j];
    const int e1 = g_expert[j + 1], p1 = g_pos[j + 1]; const float w1 = g_gate[j + 1];
    const float4* y0 = (p0 >= 0) ? (const float4*)(g_ye + ((size_t)e0 * ROWSE + b * CAP + p0) * CC) : nullptr;
    const float4* y1 = (p1 >= 0) ? (const float4*)(g_ye + ((size_t)e1 * ROWSE + b * CAP + p1) * CC) : nullptr;
    float4* o = (float4*)(out + (size_t)tok * CC);
    for (int c = threadIdx.x; c < CC / 4; c += blockDim.x) {
        float4 acc = make_float4(0.f, 0.f, 0.f, 0.f);
        if (y0) { float4 v = y0[c]; acc.x += w0 * v.x; acc.y += w0 * v.y; acc.z += w0 * v.z; acc.w += w0 * v.w; }
        if (y1) { float4 v = y1[c]; acc.x += w1 * v.x; acc.y += w1 * v.y; acc.z += w1 * v.z; acc.w += w1 * v.w; }
        o[c] = acc;
    }
}

// ---------------- launch ----------------
extern "C" void kernel_launch(void* const* d_in, const int* in_sizes, int n_in,
                              void* d_out, int out_size)
{
    const float* x   = (const float*)d_in[0];
    const float* rW1 = (const float*)d_in[1];
    const float* rb1 = (const float*)d_in[2];
    const float* rW2 = (const float*)d_in[3];
    const float* rb2 = (const float*)d_in[4];
    const float* rW3 = (const float*)d_in[5];
    const float* rb3 = (const float*)d_in[6];
    const float* eW1 = (const float*)d_in[7];
    const float* eb1 = (const float*)d_in[8];
    const float* eW2 = (const float*)d_in[9];
    const float* eb2 = (const float*)d_in[10];
    float* out = (float*)d_out;

    __half *xh, *xl, *h1h, *h1l, *xeh, *heh;
    __half *rW1h, *rW1l, *rW2h, *rW2l, *eW1h, *eW2h;
    float *h2, *ye;
    cudaGetSymbolAddress((void**)&xh, g_xh);   cudaGetSymbolAddress((void**)&xl, g_xl);
    cudaGetSymbolAddress((void**)&h1h, g_h1h); cudaGetSymbolAddress((void**)&h1l, g_h1l);
    cudaGetSymbolAddress((void**)&h2, g_h2);
    cudaGetSymbolAddress((void**)&xeh, g_xeh);
    cudaGetSymbolAddress((void**)&heh, g_heh);
    cudaGetSymbolAddress((void**)&ye, g_ye);
    cudaGetSymbolAddress((void**)&rW1h, g_rW1h); cudaGetSymbolAddress((void**)&rW1l, g_rW1l);
    cudaGetSymbolAddress((void**)&rW2h, g_rW2h); cudaGetSymbolAddress((void**)&rW2l, g_rW2l);
    cudaGetSymbolAddress((void**)&eW1h, g_eW1h);
    cudaGetSymbolAddress((void**)&eW2h, g_eW2h);

    const int smem3 = 2 * 4 * HTILE * (int)sizeof(__half);   // 81920 B
    const int smem1 = 2 * 2 * HTILE * (int)sizeof(__half);   // 40960 B
    cudaFuncSetAttribute(hmma_gemm<3, true,  1>, cudaFuncAttributeMaxDynamicSharedMemorySize, smem3);
    cudaFuncSetAttribute(hmma_gemm<3, true,  0>, cudaFuncAttributeMaxDynamicSharedMemorySize, smem3);
    cudaFuncSetAttribute(hmma_gemm<1, true,  2>, cudaFuncAttributeMaxDynamicSharedMemorySize, smem1);
    cudaFuncSetAttribute(hmma_gemm<1, false, 0>, cudaFuncAttributeMaxDynamicSharedMemorySize, smem1);

    // input split + weight transpose/split
    split_f32<<<(NTOK * CC / 4 + 255) / 256, 256>>>(x, xh, xl, (size_t)NTOK * CC);
    transpose_split_w<<<dim3(HH / 32, CC / 32, 1),  dim3(32, 8)>>>(rW1, rW1h, rW1l, CC, HH, 0, 0);
    transpose_split_w<<<dim3(HH / 32, HH / 32, 1),  dim3(32, 8)>>>(rW2, rW2h, rW2l, HH, HH, 0, 0);
    transpose_split_w<<<dim3(HH / 32, CC / 32, EE), dim3(32, 8)>>>(eW1, eW1h, nullptr, CC, HH,
        (long long)CC * HH, (long long)HH * CC);
    transpose_split_w<<<dim3(CC / 32, HH / 32, EE), dim3(32, 8)>>>(eW2, eW2h, nullptr, HH, CC,
        (long long)HH * CC, (long long)CC * HH);

    // router layer 1: h1 = relu(x @ rW1 + rb1)  (3-pass, split f16 output)
    hmma_gemm<3, true, 1><<<dim3(HH / 128, NTOK / 128, 1), 256, smem3>>>(
        xh, xl, rW1h, rW1l, rb1, nullptr, h1h, h1l, HH, CC, 0, 0, 0, 0);
    // router layer 2: h2 = relu(h1 @ rW2 + rb2)  (3-pass, f32 output)
    hmma_gemm<3, true, 0><<<dim3(HH / 128, NTOK / 128, 1), 256, smem3>>>(
        h1h, h1l, rW2h, rW2l, rb2, h2, nullptr, nullptr, HH, HH, 0, 0, 0, 0);
    // logits + softmax + top2
    router_topk<<<(NTOK * 32) / 256, 256>>>(h2, rW3, rb3);
    // capacity positions
    scan_capacity<<<BB, 256>>>();
    // dispatch
    scatter_x<<<NASN, 128>>>();
    // expert layer 1: he = relu(xe @ eW1[e] + eb1[e])  (1-pass, f16 hi output)
    hmma_gemm<1, true, 2><<<dim3(HH / 128, ROWSE / 128, EE), 256, smem1>>>(
        xeh, nullptr, eW1h, nullptr, eb1, nullptr, heh, nullptr, HH, CC,
        (long long)ROWSE * CC, (long long)HH * CC, HH, (long long)ROWSE * HH);
    // expert layer 2: ye = he @ eW2[e] + eb2[e]  (1-pass, f32 output)
    hmma_gemm<1, false, 0><<<dim3(CC / 128, ROWSE / 128, EE), 256, smem1>>>(
        heh, nullptr, eW2h, nullptr, eb2, ye, nullptr, nullptr, CC, HH,
        (long long)ROWSE * HH, (long long)CC * HH, CC, (long long)ROWSE * CC);
    // combine
    combine<<<NTOK, 256>>>(out);
}

// round 8
// speedup vs baseline: 3.1760x; 1.0865x over previous
#include <cuda_runtime.h>
#include <cuda_fp16.h>
#include <cstdint>

// ---------------- problem constants ----------------
#define BB   8
#define TT   2048
#define CC   1024
#define EE   8
#define HH   4096
#define CAP  320
#define NTOK (BB * TT)
#define NASN (NTOK * 2)
#define ROWSE (BB * CAP)          // 2560

// ---------------- scratch ----------------
static __device__ __half g_xh [(size_t)NTOK * CC],  g_xl [(size_t)NTOK * CC];
static __device__ __half g_h1h[(size_t)NTOK * HH],  g_h1l[(size_t)NTOK * HH];
static __device__ float  g_h2 [(size_t)NTOK * HH];
static __device__ __half g_xeh[(size_t)EE * ROWSE * CC];
static __device__ __half g_heh[(size_t)EE * ROWSE * HH];
static __device__ float  g_ye [(size_t)EE * ROWSE * CC];
static __device__ __half g_rW1h[(size_t)HH * CC],      g_rW1l[(size_t)HH * CC];
static __device__ __half g_rW2h[(size_t)HH * HH],      g_rW2l[(size_t)HH * HH];
static __device__ __half g_eW1h[(size_t)EE * HH * CC];
static __device__ __half g_eW2h[(size_t)EE * CC * HH];
static __device__ int    g_expert[NASN];
static __device__ float  g_gate[NASN];
static __device__ int    g_pos[NASN];

// ---------------- helpers ----------------
__device__ __forceinline__ uint32_t smem_u32(const void* p) {
    uint32_t a;
    asm("{ .reg .u64 t; cvta.to.shared.u64 t, %1; cvt.u32.u64 %0, t; }" : "=r"(a) : "l"(p));
    return a;
}
__device__ __forceinline__ void mma_f16(float* c, const uint32_t* a, uint32_t b0, uint32_t b1) {
    asm("mma.sync.aligned.m16n8k16.row.col.f32.f16.f16.f32 "
        "{%0,%1,%2,%3}, {%4,%5,%6,%7}, {%8,%9}, {%0,%1,%2,%3};"
        : "+f"(c[0]), "+f"(c[1]), "+f"(c[2]), "+f"(c[3])
        : "r"(a[0]), "r"(a[1]), "r"(a[2]), "r"(a[3]), "r"(b0), "r"(b1));
}
#define LDMX4(R, ADDR) \
    asm volatile("ldmatrix.sync.aligned.m8n8.x4.shared.b16 {%0,%1,%2,%3}, [%4];" \
        : "=r"((R)[0]), "=r"((R)[1]), "=r"((R)[2]), "=r"((R)[3]) : "r"(ADDR))
#define CPA16(DST, SRC) \
    asm volatile("cp.async.cg.shared.global [%0], [%1], 16;" :: "r"(DST), "l"(SRC))
#define CPA_COMMIT() asm volatile("cp.async.commit_group;" ::: "memory")
#define CPA_WAIT1()  asm volatile("cp.async.wait_group 1;" ::: "memory")
#define CPA_WAIT0()  asm volatile("cp.async.wait_group 0;" ::: "memory")

// smem tiles: f16, 128 rows x 32 k-halves, padded to 40 halves/row (80B stride).
// ldmatrix phases read 8 rows at stride 20 words: starts {0,20,8,28,16,4,24,12} mod 32,
// each 4 words wide -> conflict-free.
#define HPAD 40
#define HTILE (128 * HPAD)                 // halves per tile (per K32 stage slice)
#define OFF_AH 0
#define OFF_AL HTILE                       // only PASSES==3

// ---------------- FP16 mma.sync GEMM, cp.async 2-stage, K-chunk 32 ----------------
// A f16 hi(/lo) [M,K]; Bt f16 hi(/lo) [N,K]. PASSES=3: AhBh+AlBh+AhBl; PASSES=1: AhBh.
// OUT: 0 = f32, 1 = split f16 hi/lo, 2 = f16 hi only.
template <int PASSES, bool RELU, int OUT>
__global__ __launch_bounds__(256, 2)
void hmma_gemm(const __half* __restrict__ Ahg, const __half* __restrict__ Alg,
               const __half* __restrict__ Bhg, const __half* __restrict__ Blg,
               const float* __restrict__ biasg,
               float* __restrict__ Cfg, __half* __restrict__ Chg, __half* __restrict__ Clg,
               int N, int K,
               long long sA, long long sB, long long sBias, long long sC)
{
    constexpr int NT_TILES = (PASSES == 3) ? 4 : 2;
    constexpr int OFF_BH = (PASSES == 3) ? 2 * HTILE : HTILE;
    constexpr int OFF_BL = 3 * HTILE;
    constexpr int STAGE_H = NT_TILES * HTILE;        // halves per stage

    extern __shared__ __half sm[];
    const uint32_t sb = smem_u32(sm);
    const int tid  = threadIdx.x;
    const int wid  = tid >> 5;
    const int lane = tid & 31;
    const int q    = lane & 3;

    const size_t aBase = blockIdx.z * sA + (size_t)blockIdx.y * 128 * K;
    const size_t bBase = blockIdx.z * sB + (size_t)blockIdx.x * 128 * K;
    const float* bias  = biasg + blockIdx.z * sBias + blockIdx.x * 128;
    const size_t cBase = blockIdx.z * sC + (size_t)blockIdx.y * 128 * N + blockIdx.x * 128;

    const int wm = (wid & 3) * 32;      // warp tile 32x64
    const int wn = (wid >> 2) * 64;

    // ldmatrix per-lane offsets (halves within a tile)
    const int r  = lane & 7;
    const int s0 = (lane >> 3) & 1;
    const int s1 = lane >> 4;
    const uint32_t aoff0 = (uint32_t)((wm + r + (s0 << 3)) * HPAD + (s1 << 3));
    const uint32_t aoff1 = aoff0 + 16 * HPAD;
    uint32_t boff[4];
#pragma unroll
    for (int p = 0; p < 4; ++p)
        boff[p] = (uint32_t)((wn + 16 * p + r + (s1 << 3)) * HPAD + (s0 << 3));

    // cp.async loader: row = tid>>1, 32B seg = (tid&1)*32 within the 64B k-chunk row
    const int lrow = tid >> 1;
    const int lseg = (tid & 1) << 5;                 // byte offset 0 or 32
    const char* gAh = (const char*)(Ahg + aBase + (size_t)lrow * K) + lseg;
    const char* gBh = (const char*)(Bhg + bBase + (size_t)lrow * K) + lseg;
    const char* gAl = (PASSES == 3) ? (const char*)(Alg + aBase + (size_t)lrow * K) + lseg : nullptr;
    const char* gBl = (PASSES == 3) ? (const char*)(Blg + bBase + (size_t)lrow * K) + lseg : nullptr;
    const uint32_t sRow = (uint32_t)(lrow * HPAD * 2 + lseg);   // byte offset within tile

    auto issue_chunk = [&](int t, int stage) {
        const uint32_t s = sb + (uint32_t)(stage * STAGE_H * 2);
        const int go = t << 6;                        // 32 halves = 64 bytes per chunk
        CPA16(s + OFF_AH * 2 + sRow,      gAh + go);
        CPA16(s + OFF_AH * 2 + sRow + 16, gAh + go + 16);
        CPA16(s + OFF_BH * 2 + sRow,      gBh + go);
        CPA16(s + OFF_BH * 2 + sRow + 16, gBh + go + 16);
        if (PASSES == 3) {
            CPA16(s + OFF_AL * 2 + sRow,      gAl + go);
            CPA16(s + OFF_AL * 2 + sRow + 16, gAl + go + 16);
            CPA16(s + OFF_BL * 2 + sRow,      gBl + go);
            CPA16(s + OFF_BL * 2 + sRow + 16, gBl + go + 16);
        }
    };

    float acc[2][8][4];
#pragma unroll
    for (int mt = 0; mt < 2; ++mt)
#pragma unroll
        for (int nt = 0; nt < 8; ++nt)
#pragma unroll
            for (int i = 0; i < 4; ++i) acc[mt][nt][i] = 0.f;

    const int T = K >> 5;                              // K32 chunks (K >= 64 always)

    issue_chunk(0, 0); CPA_COMMIT();
    issue_chunk(1, 1); CPA_COMMIT();

    for (int t = 0; t < T; ++t) {
        if (t + 1 < T) { CPA_WAIT1(); } else { CPA_WAIT0(); }
        __syncthreads();

        const uint32_t stage = sb + (uint32_t)((t & 1) * STAGE_H * 2);
#pragma unroll
        for (int ks = 0; ks < 2; ++ks) {
            const uint32_t ko = (uint32_t)(ks << 5);   // +16 halves = +32 bytes
            uint32_t ah0[4], ah1[4], al0[4], al1[4];
            LDMX4(ah0, stage + (OFF_AH + aoff0) * 2 + ko);
            LDMX4(ah1, stage + (OFF_AH + aoff1) * 2 + ko);
            if (PASSES == 3) {
                LDMX4(al0, stage + (OFF_AL + aoff0) * 2 + ko);
                LDMX4(al1, stage + (OFF_AL + aoff1) * 2 + ko);
            }
#pragma unroll
            for (int p = 0; p < 4; ++p) {
                uint32_t bh[4], bl[4];
                LDMX4(bh, stage + (OFF_BH + boff[p]) * 2 + ko);
                if (PASSES == 3) LDMX4(bl, stage + (OFF_BL + boff[p]) * 2 + ko);
#pragma unroll
                for (int sub = 0; sub < 2; ++sub) {
                    const int nt = 2 * p + sub;
                    const uint32_t b0 = bh[2 * sub], b1 = bh[2 * sub + 1];
                    mma_f16(acc[0][nt], ah0, b0, b1);
                    mma_f16(acc[1][nt], ah1, b0, b1);
                    if (PASSES == 3) {
                        mma_f16(acc[0][nt], al0, b0, b1);
                        mma_f16(acc[1][nt], al1, b0, b1);
                        mma_f16(acc[0][nt], ah0, bl[2 * sub], bl[2 * sub + 1]);
                        mma_f16(acc[1][nt], ah1, bl[2 * sub], bl[2 * sub + 1]);
                    }
                }
            }
        }
        __syncthreads();
        if (t + 2 < T) issue_chunk(t + 2, t & 1);
        CPA_COMMIT();
    }

    // epilogue
    const int gg = lane >> 2;
#pragma unroll
    for (int nt = 0; nt < 8; ++nt) {
        const int c = wn + 8 * nt + 2 * q;
        const float b0 = bias[c], b1 = bias[c + 1];
#pragma unroll
        for (int mt = 0; mt < 2; ++mt) {
            const int rr = wm + 16 * mt + gg;
            float2 v0, v1;
            v0.x = acc[mt][nt][0] + b0; v0.y = acc[mt][nt][1] + b1;
            v1.x = acc[mt][nt][2] + b0; v1.y = acc[mt][nt][3] + b1;
            if (RELU) {
                v0.x = fmaxf(v0.x, 0.f); v0.y = fmaxf(v0.y, 0.f);
                v1.x = fmaxf(v1.x, 0.f); v1.y = fmaxf(v1.y, 0.f);
            }
            if (OUT == 0) {
                *(float2*)(Cfg + cBase + (size_t)rr * N + c)       = v0;
                *(float2*)(Cfg + cBase + (size_t)(rr + 8) * N + c) = v1;
            } else {
                __half2 h0 = __floats2half2_rn(v0.x, v0.y);
                __half2 h1 = __floats2half2_rn(v1.x, v1.y);
                *(__half2*)(Chg + cBase + (size_t)rr * N + c)       = h0;
                *(__half2*)(Chg + cBase + (size_t)(rr + 8) * N + c) = h1;
                if (OUT == 1) {
                    float2 f0 = __half22float2(h0);
                    float2 f1 = __half22float2(h1);
                    __half2 l0 = __floats2half2_rn(v0.x - f0.x, v0.y - f0.y);
                    __half2 l1 = __floats2half2_rn(v1.x - f1.x, v1.y - f1.y);
                    *(__half2*)(Clg + cBase + (size_t)rr * N + c)       = l0;
                    *(__half2*)(Clg + cBase + (size_t)(rr + 8) * N + c) = l1;
                }
            }
        }
    }
}

// ---------------- split fp32 -> f16 hi/lo ----------------
__global__ void split_f32(const float* __restrict__ in, __half* __restrict__ hi,
                          __half* __restrict__ lo, size_t n)
{
    const size_t i = ((size_t)blockIdx.x * blockDim.x + threadIdx.x) * 4;
    if (i >= n) return;
    const float4 v = *(const float4*)(in + i);
    __half2 h0 = __floats2half2_rn(v.x, v.y);
    __half2 h1 = __floats2half2_rn(v.z, v.w);
    float2 f0 = __half22float2(h0);
    float2 f1 = __half22float2(h1);
    __half2 l0 = __floats2half2_rn(v.x - f0.x, v.y - f0.y);
    __half2 l1 = __floats2half2_rn(v.z - f1.x, v.w - f1.y);
    *(__half2*)(hi + i)     = h0;
    *(__half2*)(hi + i + 2) = h1;
    *(__half2*)(lo + i)     = l0;
    *(__half2*)(lo + i + 2) = l1;
}

// ---------------- weight transpose + split ----------------
__global__ void transpose_split_w(const float* __restrict__ W,
                                  __half* __restrict__ Wth, __half* __restrict__ Wtl,
                                  int K, int N, long long sIn, long long sOut)
{
    __shared__ float s[32][33];
    const float* Wz = W + blockIdx.z * sIn;
    __half* Wh = Wth + blockIdx.z * sOut;
    __half* Wl = Wtl ? (Wtl + blockIdx.z * sOut) : nullptr;
    const int nb = blockIdx.x * 32, kbv = blockIdx.y * 32;
    const int tx = threadIdx.x, ty = threadIdx.y;
#pragma unroll
    for (int j = 0; j < 32; j += 8) s[ty + j][tx] = Wz[(size_t)(kbv + ty + j) * N + nb + tx];
    __syncthreads();
#pragma unroll
    for (int j = 0; j < 32; j += 8) {
        const float v = s[tx][ty + j];
        const __half h = __float2half_rn(v);
        Wh[(size_t)(nb + ty + j) * K + kbv + tx] = h;
        if (Wl) Wl[(size_t)(nb + ty + j) * K + kbv + tx] = __float2half_rn(v - __half2float(h));
    }
}

// ---------------- router final layer ----------------
__global__ void router_topk(const float* __restrict__ h2,
                            const float* __restrict__ rW3,
                            const float* __restrict__ rb3)
{
    const int warp = (blockIdx.x * blockDim.x + threadIdx.x) >> 5;
    const int lane = threadIdx.x & 31;
    if (warp >= NTOK) return;
    const float* hrow = h2 + (size_t)warp * HH;
    float acc[8] = {0.f, 0.f, 0.f, 0.f, 0.f, 0.f, 0.f, 0.f};
    for (int i = lane; i < HH; i += 32) {
        const float hv = hrow[i];
        const float4 w0 = *(const float4*)(rW3 + (size_t)i * 8);
        const float4 w1 = *(const float4*)(rW3 + (size_t)i * 8 + 4);
        acc[0] += hv * w0.x; acc[1] += hv * w0.y; acc[2] += hv * w0.z; acc[3] += hv * w0.w;
        acc[4] += hv * w1.x; acc[5] += hv * w1.y; acc[6] += hv * w1.z; acc[7] += hv * w1.w;
    }
#pragma unroll
    for (int e = 0; e < 8; ++e)
#pragma unroll
        for (int off = 16; off > 0; off >>= 1)
            acc[e] += __shfl_xor_sync(0xffffffffu, acc[e], off);
    if (lane == 0) {
        float lg[8], mx = -1e30f;
#pragma unroll
        for (int e = 0; e < 8; ++e) { lg[e] = acc[e] + rb3[e]; mx = fmaxf(mx, lg[e]); }
        float sm[8], sum = 0.f;
#pragma unroll
        for (int e = 0; e < 8; ++e) { sm[e] = __expf(lg[e] - mx); sum += sm[e]; }
        const float inv = 1.f / sum;
#pragma unroll
        for (int e = 0; e < 8; ++e) sm[e] *= inv;
        int e1 = 0; float v1 = sm[0];
#pragma unroll
        for (int e = 1; e < 8; ++e) if (sm[e] > v1) { v1 = sm[e]; e1 = e; }
        int e2 = -1; float v2 = -1e30f;
#pragma unroll
        for (int e = 0; e < 8; ++e) {
            if (e == e1) continue;
            if (sm[e] > v2) { v2 = sm[e]; e2 = e; }
        }
        const int j = warp * 2;
        g_expert[j] = e1;     g_gate[j] = v1;
        g_expert[j + 1] = e2; g_gate[j + 1] = v2;
    }
}

// ---------------- per-(b,e) capacity scan ----------------
__global__ void scan_capacity()
{
    __shared__ int se[TT * 2];
    const int b = blockIdx.x;
    const int base = b * (TT * 2);
    for (int i = threadIdx.x; i < TT * 2; i += blockDim.x) se[i] = g_expert[base + i];
    __syncthreads();
    const int e = threadIdx.x;
    if (e < EE) {
        int cnt = 0;
        for (int i = 0; i < TT * 2; ++i)
            if (se[i] == e) { g_pos[base + i] = (cnt < CAP) ? cnt : -1; ++cnt; }
    }
}

// ---------------- gather kept tokens ----------------
__global__ void scatter_x()
{
    const int j = blockIdx.x;
    const int pos = g_pos[j];
    if (pos < 0) return;
    const int e = g_expert[j];
    const int b = j / (TT * 2);
    const int t = (j % (TT * 2)) >> 1;
    const uint4* sh = (const uint4*)(g_xh + (size_t)(b * TT + t) * CC);
    uint4* dh = (uint4*)(g_xeh + ((size_t)e * ROWSE + b * CAP + pos) * CC);
    for (int c = threadIdx.x; c < CC / 8; c += blockDim.x) dh[c] = sh[c];
}

// ---------------- combine ----------------
__global__ void combine(float* __restrict__ out)
{
    const int tok = blockIdx.x;
    const int b = tok / TT;
    const int j = tok * 2;
    const int e0 = g_expert[j],     p0 = g_pos[j];     const float w0 = g_gate[j];
    const int e1 = g_expert[j + 1], p1 = g_pos[j + 1]; const float w1 = g_gate[j + 1];
    const float4* y0 = (p0 >= 0) ? (const float4*)(g_ye + ((size_t)e0 * ROWSE + b * CAP + p0) * CC) : nullptr;
    const float4* y1 = (p1 >= 0) ? (const float4*)(g_ye + ((size_t)e1 * ROWSE + b * CAP + p1) * CC) : nullptr;
    float4* o = (float4*)(out + (size_t)tok * CC);
    for (int c = threadIdx.x; c < CC / 4; c += blockDim.x) {
        float4 acc = make_float4(0.f, 0.f, 0.f, 0.f);
        if (y0) { float4 v = y0[c]; acc.x += w0 * v.x; acc.y += w0 * v.y; acc.z += w0 * v.z; acc.w += w0 * v.w; }
        if (y1) { float4 v = y1[c]; acc.x += w1 * v.x; acc.y += w1 * v.y; acc.z += w1 * v.z; acc.w += w1 * v.w; }
        o[c] = acc;
    }
}

// ---------------- launch ----------------
extern "C" void kernel_launch(void* const* d_in, const int* in_sizes, int n_in,
                              void* d_out, int out_size)
{
    const float* x   = (const float*)d_in[0];
    const float* rW1 = (const float*)d_in[1];
    const float* rb1 = (const float*)d_in[2];
    const float* rW2 = (const float*)d_in[3];
    const float* rb2 = (const float*)d_in[4];
    const float* rW3 = (const float*)d_in[5];
    const float* rb3 = (const float*)d_in[6];
    const float* eW1 = (const float*)d_in[7];
    const float* eb1 = (const float*)d_in[8];
    const float* eW2 = (const float*)d_in[9];
    const float* eb2 = (const float*)d_in[10];
    float* out = (float*)d_out;

    __half *xh, *xl, *h1h, *h1l, *xeh, *heh;
    __half *rW1h, *rW1l, *rW2h, *rW2l, *eW1h, *eW2h;
    float *h2, *ye;
    cudaGetSymbolAddress((void**)&xh, g_xh);   cudaGetSymbolAddress((void**)&xl, g_xl);
    cudaGetSymbolAddress((void**)&h1h, g_h1h); cudaGetSymbolAddress((void**)&h1l, g_h1l);
    cudaGetSymbolAddress((void**)&h2, g_h2);
    cudaGetSymbolAddress((void**)&xeh, g_xeh);
    cudaGetSymbolAddress((void**)&heh, g_heh);
    cudaGetSymbolAddress((void**)&ye, g_ye);
    cudaGetSymbolAddress((void**)&rW1h, g_rW1h); cudaGetSymbolAddress((void**)&rW1l, g_rW1l);
    cudaGetSymbolAddress((void**)&rW2h, g_rW2h); cudaGetSymbolAddress((void**)&rW2l, g_rW2l);
    cudaGetSymbolAddress((void**)&eW1h, g_eW1h);
    cudaGetSymbolAddress((void**)&eW2h, g_eW2h);

    const int smem3 = 2 * 4 * HTILE * (int)sizeof(__half);   // 81920 B
    const int smem1 = 2 * 2 * HTILE * (int)sizeof(__half);   // 40960 B
    cudaFuncSetAttribute(hmma_gemm<3, true,  1>, cudaFuncAttributeMaxDynamicSharedMemorySize, smem3);
    cudaFuncSetAttribute(hmma_gemm<3, true,  0>, cudaFuncAttributeMaxDynamicSharedMemorySize, smem3);
    cudaFuncSetAttribute(hmma_gemm<1, true,  2>, cudaFuncAttributeMaxDynamicSharedMemorySize, smem1);
    cudaFuncSetAttribute(hmma_gemm<1, false, 0>, cudaFuncAttributeMaxDynamicSharedMemorySize, smem1);

    // input split + weight transpose/split
    split_f32<<<(NTOK * CC / 4 + 255) / 256, 256>>>(x, xh, xl, (size_t)NTOK * CC);
    transpose_split_w<<<dim3(HH / 32, CC / 32, 1),  dim3(32, 8)>>>(rW1, rW1h, rW1l, CC, HH, 0, 0);
    transpose_split_w<<<dim3(HH / 32, HH / 32, 1),  dim3(32, 8)>>>(rW2, rW2h, rW2l, HH, HH, 0, 0);
    transpose_split_w<<<dim3(HH / 32, CC / 32, EE), dim3(32, 8)>>>(eW1, eW1h, nullptr, CC, HH,
        (long long)CC * HH, (long long)HH * CC);
    transpose_split_w<<<dim3(CC / 32, HH / 32, EE), dim3(32, 8)>>>(eW2, eW2h, nullptr, HH, CC,
        (long long)HH * CC, (long long)CC * HH);

    // router layer 1: h1 = relu(x @ rW1 + rb1)  (3-pass, split f16 output)
    hmma_gemm<3, true, 1><<<dim3(HH / 128, NTOK / 128, 1), 256, smem3>>>(
        xh, xl, rW1h, rW1l, rb1, nullptr, h1h, h1l, HH, CC, 0, 0, 0, 0);
    // router layer 2: h2 = relu(h1 @ rW2 + rb2)  (3-pass, f32 output)
    hmma_gemm<3, true, 0><<<dim3(HH / 128, NTOK / 128, 1), 256, smem3>>>(
        h1h, h1l, rW2h, rW2l, rb2, h2, nullptr, nullptr, HH, HH, 0, 0, 0, 0);
    // logits + softmax + top2
    router_topk<<<(NTOK * 32) / 256, 256>>>(h2, rW3, rb3);
    // capacity positions
    scan_capacity<<<BB, 256>>>();
    // dispatch
    scatter_x<<<NASN, 128>>>();
    // expert layer 1: he = relu(xe @ eW1[e] + eb1[e])  (1-pass, f16 hi output)
    hmma_gemm<1, true, 2><<<dim3(HH / 128, ROWSE / 128, EE), 256, smem1>>>(
        xeh, nullptr, eW1h, nullptr, eb1, nullptr, heh, nullptr, HH, CC,
        (long long)ROWSE * CC, (long long)HH * CC, HH, (long long)ROWSE * HH);
    // expert layer 2: ye = he @ eW2[e] + eb2[e]  (1-pass, f32 output)
    hmma_gemm<1, false, 0><<<dim3(CC / 128, ROWSE / 128, EE), 256, smem1>>>(
        heh, nullptr, eW2h, nullptr, eb2, ye, nullptr, nullptr, CC, HH,
        (long long)ROWSE * HH, (long long)CC * HH, CC, (long long)ROWSE * CC);
    // combine
    combine<<<NTOK, 256>>>(out);
}

// round 9
// speedup vs baseline: 3.6322x; 1.1437x over previous
#include <cuda_runtime.h>
#include <cuda_fp16.h>
#include <cstdint>

// ---------------- problem constants ----------------
#define BB   8
#define TT   2048
#define CC   1024
#define EE   8
#define HH   4096
#define CAP  320
#define NTOK (BB * TT)
#define NASN (NTOK * 2)
#define ROWSE (BB * CAP)          // 2560

// ---------------- scratch ----------------
static __device__ __half g_xh [(size_t)NTOK * CC],  g_xl [(size_t)NTOK * CC];
static __device__ __half g_h1h[(size_t)NTOK * HH],  g_h1l[(size_t)NTOK * HH];
static __device__ float  g_h2 [(size_t)NTOK * HH];
static __device__ __half g_xeh[(size_t)EE * ROWSE * CC];
static __device__ __half g_heh[(size_t)EE * ROWSE * HH];
static __device__ float  g_ye [(size_t)EE * ROWSE * CC];
static __device__ __half g_rW1h[(size_t)HH * CC],      g_rW1l[(size_t)HH * CC];
static __device__ __half g_rW2h[(size_t)HH * HH],      g_rW2l[(size_t)HH * HH];
static __device__ __half g_eW1h[(size_t)EE * HH * CC];
static __device__ __half g_eW2h[(size_t)EE * CC * HH];
static __device__ int    g_expert[NASN];
static __device__ float  g_gate[NASN];
static __device__ int    g_pos[NASN];

// ---------------- helpers ----------------
__device__ __forceinline__ uint32_t smem_u32(const void* p) {
    uint32_t a;
    asm("{ .reg .u64 t; cvta.to.shared.u64 t, %1; cvt.u32.u64 %0, t; }" : "=r"(a) : "l"(p));
    return a;
}
__device__ __forceinline__ void mma_f16(float* c, const uint32_t* a, uint32_t b0, uint32_t b1) {
    asm("mma.sync.aligned.m16n8k16.row.col.f32.f16.f16.f32 "
        "{%0,%1,%2,%3}, {%4,%5,%6,%7}, {%8,%9}, {%0,%1,%2,%3};"
        : "+f"(c[0]), "+f"(c[1]), "+f"(c[2]), "+f"(c[3])
        : "r"(a[0]), "r"(a[1]), "r"(a[2]), "r"(a[3]), "r"(b0), "r"(b1));
}
#define LDMX4(R, ADDR) \
    asm volatile("ldmatrix.sync.aligned.m8n8.x4.shared.b16 {%0,%1,%2,%3}, [%4];" \
        : "=r"((R)[0]), "=r"((R)[1]), "=r"((R)[2]), "=r"((R)[3]) : "r"(ADDR))
#define CPA16(DST, SRC) \
    asm volatile("cp.async.cg.shared.global [%0], [%1], 16;" :: "r"(DST), "l"(SRC))
#define CPA_COMMIT() asm volatile("cp.async.commit_group;" ::: "memory")
#define CPA_WAIT1()  asm volatile("cp.async.wait_group 1;" ::: "memory")

// tile: 128 rows x 64 B (32 halves). phys(row, chunk) = row*64 + ((chunk ^ ((row>>1)&3))<<4)
// 8-row x 16B ldmatrix phases: even rows cover all 4 chunk slots (banks 0-15),
// odd rows cover banks 16-31 -> conflict-free.
#define TILEB 8192
__device__ __forceinline__ uint32_t physoff(int row, int chunk) {
    return (uint32_t)(row * 64 + (((chunk) ^ ((row >> 1) & 3)) << 4));
}

// ---------------- FP16 mma.sync GEMM, cp.async 3-stage, K-chunk 32, 1 sync/chunk ----
// A f16 hi(/lo) [M,K]; Bt f16 hi(/lo) [N,K]. PASSES=3: AhBh+AlBh+AhBl; PASSES=1: AhBh.
// OUT: 0 = f32, 1 = split f16 hi/lo, 2 = f16 hi only.
template <int PASSES, bool RELU, int OUT>
__global__ __launch_bounds__(256, 2)
void hmma_gemm(const __half* __restrict__ Ahg, const __half* __restrict__ Alg,
               const __half* __restrict__ Bhg, const __half* __restrict__ Blg,
               const float* __restrict__ biasg,
               float* __restrict__ Cfg, __half* __restrict__ Chg, __half* __restrict__ Clg,
               int N, int K,
               long long sA, long long sB, long long sBias, long long sC)
{
    constexpr int NT_TILES = (PASSES == 3) ? 4 : 2;
    constexpr uint32_t OFF_AH = 0;
    constexpr uint32_t OFF_AL = TILEB;                 // only PASSES==3
    constexpr uint32_t OFF_BH = (PASSES == 3) ? 2 * TILEB : TILEB;
    constexpr uint32_t OFF_BL = 3 * TILEB;
    constexpr uint32_t STAGE_B = NT_TILES * TILEB;

    extern __shared__ __half sm[];
    const uint32_t sb = smem_u32(sm);
    const int tid  = threadIdx.x;
    const int wid  = tid >> 5;
    const int lane = tid & 31;
    const int q    = lane & 3;

    const size_t aBase = blockIdx.z * sA + (size_t)blockIdx.y * 128 * K;
    const size_t bBase = blockIdx.z * sB + (size_t)blockIdx.x * 128 * K;
    const float* bias  = biasg + blockIdx.z * sBias + blockIdx.x * 128;
    const size_t cBase = blockIdx.z * sC + (size_t)blockIdx.y * 128 * N + blockIdx.x * 128;

    const int wm = (wid & 3) * 32;      // warp tile 32x64
    const int wn = (wid >> 2) * 64;

    // ldmatrix per-lane byte offsets within a tile (swizzled), [mt or p][ks]
    const int r  = lane & 7;
    const int s0 = (lane >> 3) & 1;
    const int s1 = lane >> 4;
    uint32_t aoff[2][2], boff[4][2];
#pragma unroll
    for (int mt = 0; mt < 2; ++mt)
#pragma unroll
        for (int ks = 0; ks < 2; ++ks)
            aoff[mt][ks] = physoff(wm + 16 * mt + r + (s0 << 3), 2 * ks + s1);
#pragma unroll
    for (int p = 0; p < 4; ++p)
#pragma unroll
        for (int ks = 0; ks < 2; ++ks)
            boff[p][ks] = physoff(wn + 16 * p + r + (s1 << 3), 2 * ks + s0);

    // cp.async loader: row = tid>>1, seg = tid&1 -> logical chunks {2seg, 2seg+1}
    const int lrow = tid >> 1;
    const int lseg = tid & 1;
    const char* gAh = (const char*)(Ahg + aBase + (size_t)lrow * K) + lseg * 32;
    const char* gBh = (const char*)(Bhg + bBase + (size_t)lrow * K) + lseg * 32;
    const char* gAl = (PASSES == 3) ? (const char*)(Alg + aBase + (size_t)lrow * K) + lseg * 32 : nullptr;
    const char* gBl = (PASSES == 3) ? (const char*)(Blg + bBase + (size_t)lrow * K) + lseg * 32 : nullptr;
    const uint32_t d0 = physoff(lrow, 2 * lseg);
    const uint32_t d1 = physoff(lrow, 2 * lseg + 1);

    auto issue_chunk = [&](int t, int stage) {
        const uint32_t s = sb + (uint32_t)stage * STAGE_B;
        const int go = t << 6;                        // 64 bytes per chunk
        CPA16(s + OFF_AH + d0, gAh + go);
        CPA16(s + OFF_AH + d1, gAh + go + 16);
        CPA16(s + OFF_BH + d0, gBh + go);
        CPA16(s + OFF_BH + d1, gBh + go + 16);
        if (PASSES == 3) {
            CPA16(s + OFF_AL + d0, gAl + go);
            CPA16(s + OFF_AL + d1, gAl + go + 16);
            CPA16(s + OFF_BL + d0, gBl + go);
            CPA16(s + OFF_BL + d1, gBl + go + 16);
        }
    };

    float acc[2][8][4];
#pragma unroll
    for (int mt = 0; mt < 2; ++mt)
#pragma unroll
        for (int nt = 0; nt < 8; ++nt)
#pragma unroll
            for (int i = 0; i < 4; ++i) acc[mt][nt][i] = 0.f;

    const int T = K >> 5;

    issue_chunk(0, 0); CPA_COMMIT();
    issue_chunk(1, 1); CPA_COMMIT();

    int cur = 0;
    for (int t = 0; t < T; ++t) {
        CPA_WAIT1();                    // chunk t landed
        __syncthreads();                // visibility + all warps done reading stage (t-1)%3
        const int iss = (cur == 0) ? 2 : cur - 1;   // (t+2)%3
        if (t + 2 < T) issue_chunk(t + 2, iss);
        CPA_COMMIT();

        const uint32_t stage = sb + (uint32_t)cur * STAGE_B;
#pragma unroll
        for (int ks = 0; ks < 2; ++ks) {
            uint32_t ah0[4], ah1[4], al0[4], al1[4];
            LDMX4(ah0, stage + OFF_AH + aoff[0][ks]);
            LDMX4(ah1, stage + OFF_AH + aoff[1][ks]);
            if (PASSES == 3) {
                LDMX4(al0, stage + OFF_AL + aoff[0][ks]);
                LDMX4(al1, stage + OFF_AL + aoff[1][ks]);
            }
#pragma unroll
            for (int p = 0; p < 4; ++p) {
                uint32_t bh[4], bl[4];
                LDMX4(bh, stage + OFF_BH + boff[p][ks]);
                if (PASSES == 3) LDMX4(bl, stage + OFF_BL + boff[p][ks]);
#pragma unroll
                for (int sub = 0; sub < 2; ++sub) {
                    const int nt = 2 * p + sub;
                    const uint32_t b0 = bh[2 * sub], b1 = bh[2 * sub + 1];
                    mma_f16(acc[0][nt], ah0, b0, b1);
                    mma_f16(acc[1][nt], ah1, b0, b1);
                    if (PASSES == 3) {
                        mma_f16(acc[0][nt], al0, b0, b1);
                        mma_f16(acc[1][nt], al1, b0, b1);
                        mma_f16(acc[0][nt], ah0, bl[2 * sub], bl[2 * sub + 1]);
                        mma_f16(acc[1][nt], ah1, bl[2 * sub], bl[2 * sub + 1]);
                    }
                }
            }
        }
        cur = (cur == 2) ? 0 : cur + 1;
    }

    // epilogue
    const int gg = lane >> 2;
#pragma unroll
    for (int nt = 0; nt < 8; ++nt) {
        const int c = wn + 8 * nt + 2 * q;
        const float b0 = bias[c], b1 = bias[c + 1];
#pragma unroll
        for (int mt = 0; mt < 2; ++mt) {
            const int rr = wm + 16 * mt + gg;
            float2 v0, v1;
            v0.x = acc[mt][nt][0] + b0; v0.y = acc[mt][nt][1] + b1;
            v1.x = acc[mt][nt][2] + b0; v1.y = acc[mt][nt][3] + b1;
            if (RELU) {
                v0.x = fmaxf(v0.x, 0.f); v0.y = fmaxf(v0.y, 0.f);
                v1.x = fmaxf(v1.x, 0.f); v1.y = fmaxf(v1.y, 0.f);
            }
            if (OUT == 0) {
                *(float2*)(Cfg + cBase + (size_t)rr * N + c)       = v0;
                *(float2*)(Cfg + cBase + (size_t)(rr + 8) * N + c) = v1;
            } else {
                __half2 h0 = __floats2half2_rn(v0.x, v0.y);
                __half2 h1 = __floats2half2_rn(v1.x, v1.y);
                *(__half2*)(Chg + cBase + (size_t)rr * N + c)       = h0;
                *(__half2*)(Chg + cBase + (size_t)(rr + 8) * N + c) = h1;
                if (OUT == 1) {
                    float2 f0 = __half22float2(h0);
                    float2 f1 = __half22float2(h1);
                    __half2 l0 = __floats2half2_rn(v0.x - f0.x, v0.y - f0.y);
                    __half2 l1 = __floats2half2_rn(v1.x - f1.x, v1.y - f1.y);
                    *(__half2*)(Clg + cBase + (size_t)rr * N + c)       = l0;
                    *(__half2*)(Clg + cBase + (size_t)(rr + 8) * N + c) = l1;
                }
            }
        }
    }
}

// ---------------- split fp32 -> f16 hi/lo ----------------
__global__ void split_f32(const float* __restrict__ in, __half* __restrict__ hi,
                          __half* __restrict__ lo, size_t n)
{
    const size_t i = ((size_t)blockIdx.x * blockDim.x + threadIdx.x) * 4;
    if (i >= n) return;
    const float4 v = *(const float4*)(in + i);
    __half2 h0 = __floats2half2_rn(v.x, v.y);
    __half2 h1 = __floats2half2_rn(v.z, v.w);
    float2 f0 = __half22float2(h0);
    float2 f1 = __half22float2(h1);
    __half2 l0 = __floats2half2_rn(v.x - f0.x, v.y - f0.y);
    __half2 l1 = __floats2half2_rn(v.z - f1.x, v.w - f1.y);
    *(__half2*)(hi + i)     = h0;
    *(__half2*)(hi + i + 2) = h1;
    *(__half2*)(lo + i)     = l0;
    *(__half2*)(lo + i + 2) = l1;
}

// ---------------- weight transpose + split ----------------
__global__ void transpose_split_w(const float* __restrict__ W,
                                  __half* __restrict__ Wth, __half* __restrict__ Wtl,
                                  int K, int N, long long sIn, long long sOut)
{
    __shared__ float s[32][33];
    const float* Wz = W + blockIdx.z * sIn;
    __half* Wh = Wth + blockIdx.z * sOut;
    __half* Wl = Wtl ? (Wtl + blockIdx.z * sOut) : nullptr;
    const int nb = blockIdx.x * 32, kbv = blockIdx.y * 32;
    const int tx = threadIdx.x, ty = threadIdx.y;
#pragma unroll
    for (int j = 0; j < 32; j += 8) s[ty + j][tx] = Wz[(size_t)(kbv + ty + j) * N + nb + tx];
    __syncthreads();
#pragma unroll
    for (int j = 0; j < 32; j += 8) {
        const float v = s[tx][ty + j];
        const __half h = __float2half_rn(v);
        Wh[(size_t)(nb + ty + j) * K + kbv + tx] = h;
        if (Wl) Wl[(size_t)(nb + ty + j) * K + kbv + tx] = __float2half_rn(v - __half2float(h));
    }
}

// ---------------- router final layer ----------------
__global__ void router_topk(const float* __restrict__ h2,
                            const float* __restrict__ rW3,
                            const float* __restrict__ rb3)
{
    const int warp = (blockIdx.x * blockDim.x + threadIdx.x) >> 5;
    const int lane = threadIdx.x & 31;
    if (warp >= NTOK) return;
    const float* hrow = h2 + (size_t)warp * HH;
    float acc[8] = {0.f, 0.f, 0.f, 0.f, 0.f, 0.f, 0.f, 0.f};
    for (int i = lane; i < HH; i += 32) {
        const float hv = hrow[i];
        const float4 w0 = *(const float4*)(rW3 + (size_t)i * 8);
        const float4 w1 = *(const float4*)(rW3 + (size_t)i * 8 + 4);
        acc[0] += hv * w0.x; acc[1] += hv * w0.y; acc[2] += hv * w0.z; acc[3] += hv * w0.w;
        acc[4] += hv * w1.x; acc[5] += hv * w1.y; acc[6] += hv * w1.z; acc[7] += hv * w1.w;
    }
#pragma unroll
    for (int e = 0; e < 8; ++e)
#pragma unroll
        for (int off = 16; off > 0; off >>= 1)
            acc[e] += __shfl_xor_sync(0xffffffffu, acc[e], off);
    if (lane == 0) {
        float lg[8], mx = -1e30f;
#pragma unroll
        for (int e = 0; e < 8; ++e) { lg[e] = acc[e] + rb3[e]; mx = fmaxf(mx, lg[e]); }
        float sm[8], sum = 0.f;
#pragma unroll
        for (int e = 0; e < 8; ++e) { sm[e] = __expf(lg[e] - mx); sum += sm[e]; }
        const float inv = 1.f / sum;
#pragma unroll
        for (int e = 0; e < 8; ++e) sm[e] *= inv;
        int e1 = 0; float v1 = sm[0];
#pragma unroll
        for (int e = 1; e < 8; ++e) if (sm[e] > v1) { v1 = sm[e]; e1 = e; }
        int e2 = -1; float v2 = -1e30f;
#pragma unroll
        for (int e = 0; e < 8; ++e) {
            if (e == e1) continue;
            if (sm[e] > v2) { v2 = sm[e]; e2 = e; }
        }
        const int j = warp * 2;
        g_expert[j] = e1;     g_gate[j] = v1;
        g_expert[j + 1] = e2; g_gate[j + 1] = v2;
    }
}

// ---------------- per-(b,e) capacity scan: warp ballot scan ----------------
__global__ void scan_capacity()
{
    __shared__ int se[TT * 2];
    const int b = blockIdx.x;
    const int base = b * (TT * 2);
    for (int i = threadIdx.x; i < TT * 2; i += blockDim.x) se[i] = g_expert[base + i];
    __syncthreads();
    const int e = threadIdx.x >> 5;      // warp = expert (8 warps)
    const int lane = threadIdx.x & 31;
    int cnt = 0;
    for (int i0 = 0; i0 < TT * 2; i0 += 32) {
        const bool m = (se[i0 + lane] == e);
        const unsigned bal = __ballot_sync(0xffffffffu, m);
        if (m) {
            const int pos = cnt + __popc(bal & ((1u << lane) - 1));
            g_pos[base + i0 + lane] = (pos < CAP) ? pos : -1;
        }
        cnt += __popc(bal);
    }
}

// ---------------- gather kept tokens ----------------
__global__ void scatter_x()
{
    const int j = blockIdx.x;
    const int pos = g_pos[j];
    if (pos < 0) return;
    const int e = g_expert[j];
    const int b = j / (TT * 2);
    const int t = (j % (TT * 2)) >> 1;
    const uint4* sh = (const uint4*)(g_xh + (size_t)(b * TT + t) * CC);
    uint4* dh = (uint4*)(g_xeh + ((size_t)e * ROWSE + b * CAP + pos) * CC);
    for (int c = threadIdx.x; c < CC / 8; c += blockDim.x) dh[c] = sh[c];
}

// ---------------- combine ----------------
__global__ void combine(float* __restrict__ out)
{
    const int tok = blockIdx.x;
    const int b = tok / TT;
    const int j = tok * 2;
    const int e0 = g_expert[j],     p0 = g_pos[j];     const float w0 = g_gate[j];
    const int e1 = g_expert[j + 1], p1 = g_pos[j + 1]; const float w1 = g_gate[j + 1];
    const float4* y0 = (p0 >= 0) ? (const float4*)(g_ye + ((size_t)e0 * ROWSE + b * CAP + p0) * CC) : nullptr;
    const float4* y1 = (p1 >= 0) ? (const float4*)(g_ye + ((size_t)e1 * ROWSE + b * CAP + p1) * CC) : nullptr;
    float4* o = (float4*)(out + (size_t)tok * CC);
    for (int c = threadIdx.x; c < CC / 4; c += blockDim.x) {
        float4 acc = make_float4(0.f, 0.f, 0.f, 0.f);
        if (y0) { float4 v = y0[c]; acc.x += w0 * v.x; acc.y += w0 * v.y; acc.z += w0 * v.z; acc.w += w0 * v.w; }
        if (y1) { float4 v = y1[c]; acc.x += w1 * v.x; acc.y += w1 * v.y; acc.z += w1 * v.z; acc.w += w1 * v.w; }
        o[c] = acc;
    }
}

// ---------------- launch ----------------
extern "C" void kernel_launch(void* const* d_in, const int* in_sizes, int n_in,
                              void* d_out, int out_size)
{
    const float* x   = (const float*)d_in[0];
    const float* rW1 = (const float*)d_in[1];
    const float* rb1 = (const float*)d_in[2];
    const float* rW2 = (const float*)d_in[3];
    const float* rb2 = (const float*)d_in[4];
    const float* rW3 = (const float*)d_in[5];
    const float* rb3 = (const float*)d_in[6];
    const float* eW1 = (const float*)d_in[7];
    const float* eb1 = (const float*)d_in[8];
    const float* eW2 = (const float*)d_in[9];
    const float* eb2 = (const float*)d_in[10];
    float* out = (float*)d_out;

    __half *xh, *xl, *h1h, *h1l, *xeh, *heh;
    __half *rW1h, *rW1l, *rW2h, *rW2l, *eW1h, *eW2h;
    float *h2, *ye;
    cudaGetSymbolAddress((void**)&xh, g_xh);   cudaGetSymbolAddress((void**)&xl, g_xl);
    cudaGetSymbolAddress((void**)&h1h, g_h1h); cudaGetSymbolAddress((void**)&h1l, g_h1l);
    cudaGetSymbolAddress((void**)&h2, g_h2);
    cudaGetSymbolAddress((void**)&xeh, g_xeh);
    cudaGetSymbolAddress((void**)&heh, g_heh);
    cudaGetSymbolAddress((void**)&ye, g_ye);
    cudaGetSymbolAddress((void**)&rW1h, g_rW1h); cudaGetSymbolAddress((void**)&rW1l, g_rW1l);
    cudaGetSymbolAddress((void**)&rW2h, g_rW2h); cudaGetSymbolAddress((void**)&rW2l, g_rW2l);
    cudaGetSymbolAddress((void**)&eW1h, g_eW1h);
    cudaGetSymbolAddress((void**)&eW2h, g_eW2h);

    const int smem3 = 3 * 4 * TILEB;   // 98304 B
    const int smem1 = 3 * 2 * TILEB;   // 49152 B
    cudaFuncSetAttribute(hmma_gemm<3, true,  1>, cudaFuncAttributeMaxDynamicSharedMemorySize, smem3);
    cudaFuncSetAttribute(hmma_gemm<3, true,  0>, cudaFuncAttributeMaxDynamicSharedMemorySize, smem3);
    cudaFuncSetAttribute(hmma_gemm<1, true,  2>, cudaFuncAttributeMaxDynamicSharedMemorySize, smem1);
    cudaFuncSetAttribute(hmma_gemm<1, false, 0>, cudaFuncAttributeMaxDynamicSharedMemorySize, smem1);

    // input split + weight transpose/split
    split_f32<<<(NTOK * CC / 4 + 255) / 256, 256>>>(x, xh, xl, (size_t)NTOK * CC);
    transpose_split_w<<<dim3(HH / 32, CC / 32, 1),  dim3(32, 8)>>>(rW1, rW1h, rW1l, CC, HH, 0, 0);
    transpose_split_w<<<dim3(HH / 32, HH / 32, 1),  dim3(32, 8)>>>(rW2, rW2h, rW2l, HH, HH, 0, 0);
    transpose_split_w<<<dim3(HH / 32, CC / 32, EE), dim3(32, 8)>>>(eW1, eW1h, nullptr, CC, HH,
        (long long)CC * HH, (long long)HH * CC);
    transpose_split_w<<<dim3(CC / 32, HH / 32, EE), dim3(32, 8)>>>(eW2, eW2h, nullptr, HH, CC,
        (long long)HH * CC, (long long)CC * HH);

    // router layer 1: h1 = relu(x @ rW1 + rb1)  (3-pass, split f16 output)
    hmma_gemm<3, true, 1><<<dim3(HH / 128, NTOK / 128, 1), 256, smem3>>>(
        xh, xl, rW1h, rW1l, rb1, nullptr, h1h, h1l, HH, CC, 0, 0, 0, 0);
    // router layer 2: h2 = relu(h1 @ rW2 + rb2)  (3-pass, f32 output)
    hmma_gemm<3, true, 0><<<dim3(HH / 128, NTOK / 128, 1), 256, smem3>>>(
        h1h, h1l, rW2h, rW2l, rb2, h2, nullptr, nullptr, HH, HH, 0, 0, 0, 0);
    // logits + softmax + top2
    router_topk<<<(NTOK * 32) / 256, 256>>>(h2, rW3, rb3);
    // capacity positions
    scan_capacity<<<BB, 256>>>();
    // dispatch
    scatter_x<<<NASN, 128>>>();
    // expert layer 1: he = relu(xe @ eW1[e] + eb1[e])  (1-pass, f16 hi output)
    hmma_gemm<1, true, 2><<<dim3(HH / 128, ROWSE / 128, EE), 256, smem1>>>(
        xeh, nullptr, eW1h, nullptr, eb1, nullptr, heh, nullptr, HH, CC,
        (long long)ROWSE * CC, (long long)HH * CC, HH, (long long)ROWSE * HH);
    // expert layer 2: ye = he @ eW2[e] + eb2[e]  (1-pass, f32 output)
    hmma_gemm<1, false, 0><<<dim3(CC / 128, ROWSE / 128, EE), 256, smem1>>>(
        heh, nullptr, eW2h, nullptr, eb2, ye, nullptr, nullptr, CC, HH,
        (long long)ROWSE * HH, (long long)CC * HH, CC, (long long)ROWSE * CC);
    // combine
    combine<<<NTOK, 256>>>(out);
}